// round 1
// baseline (speedup 1.0000x reference)
#include <cuda_runtime.h>
#include <math.h>

// ---------------- scratch (device globals; no runtime allocation) ----------------
#define NMAX 50000
#define EMAX 400000

__device__ float g_hln[(size_t)NMAX * 128];   // h_ln -> later h_attn -> later hn
__device__ float g_eln[(size_t)EMAX * 128];   // e_ln -> later en
__device__ float g_Q  [(size_t)NMAX * 128];
__device__ float g_Kb [(size_t)NMAX * 128];
__device__ float g_Vb [(size_t)NMAX * 128];
__device__ float g_PE [(size_t)EMAX * 128];   // PE -> overwritten in place with e_attn
__device__ float g_wV [(size_t)NMAX * 128];
__device__ float g_z  [(size_t)NMAX * 8];
__device__ float g_h2 [(size_t)NMAX * 128];
__device__ float g_e2 [(size_t)EMAX * 128];
__device__ float g_tn [(size_t)NMAX * 256];
__device__ float g_te [(size_t)EMAX * 256];

// ---------------- LayerNorm: one warp per row of 128 ----------------
__global__ void ln_kernel(const float* __restrict__ x, const float* __restrict__ g,
                          const float* __restrict__ b, float* __restrict__ y, int rows) {
    int row = blockIdx.x * 8 + (threadIdx.x >> 5);
    if (row >= rows) return;
    int lane = threadIdx.x & 31;
    const float4 v = *(const float4*)(x + (size_t)row * 128 + lane * 4);
    float s = v.x + v.y + v.z + v.w;
#pragma unroll
    for (int o = 16; o; o >>= 1) s += __shfl_xor_sync(0xffffffffu, s, o);
    float mu = s * 0.0078125f;
    float d0 = v.x - mu, d1 = v.y - mu, d2 = v.z - mu, d3 = v.w - mu;
    float q = d0 * d0 + d1 * d1 + d2 * d2 + d3 * d3;
#pragma unroll
    for (int o = 16; o; o >>= 1) q += __shfl_xor_sync(0xffffffffu, q, o);
    float inv = rsqrtf(q * 0.0078125f + 1e-5f);
    float4 gg = *(const float4*)(g + lane * 4);
    float4 bb = *(const float4*)(b + lane * 4);
    float4 o;
    o.x = d0 * inv * gg.x + bb.x;
    o.y = d1 * inv * gg.y + bb.y;
    o.z = d2 * inv * gg.z + bb.z;
    o.w = d3 * inv * gg.w + bb.w;
    *(float4*)(y + (size_t)row * 128 + lane * 4) = o;
}

// ---------------- zero fill ----------------
__global__ void zero_kernel(float* __restrict__ a, size_t n) {
    size_t i = (size_t)blockIdx.x * blockDim.x + threadIdx.x;
    size_t stride = (size_t)gridDim.x * blockDim.x;
    for (; i < n; i += stride) a[i] = 0.0f;
}

// ---------------- tiled SGEMM: C[M,Ntot] = A[M,K] @ B[K,Ntot], epilogues ----------
// EPI: 0 = none, 1 = +bias +residual, 2 = silu, 3 = +residual
// CTA tile 64x128, 256 threads, 4x8 micro-tile, K processed in 128-chunks.
template <int EPI>
__global__ void gemm_kernel(const float* __restrict__ A, const float* __restrict__ B,
                            float* __restrict__ C, const float* __restrict__ bias,
                            const float* __restrict__ R, int M, int K, int Ntot) {
    extern __shared__ float sm[];
    float* As = sm;             // [128][64]  (transposed A tile)
    float* Bs = sm + 128 * 64;  // [128][128]
    const int tid = threadIdx.x;
    const int tx = tid & 15, ty = tid >> 4;
    const int m0 = blockIdx.x * 64;
    const int n0 = blockIdx.y * 128;

    float acc[4][8];
#pragma unroll
    for (int r = 0; r < 4; r++)
#pragma unroll
        for (int c = 0; c < 8; c++) acc[r][c] = 0.0f;

    for (int kc = 0; kc < K; kc += 128) {
        // load A tile (64 rows x 128 k), store transposed
#pragma unroll
        for (int i = 0; i < 8; i++) {
            int idx = tid + i * 256;       // 0..2047
            int row = idx >> 5;            // 0..63
            int kv = (idx & 31) << 2;      // 0..124
            float4 v = make_float4(0.f, 0.f, 0.f, 0.f);
            if (m0 + row < M) v = *(const float4*)(A + (size_t)(m0 + row) * K + kc + kv);
            As[(kv + 0) * 64 + row] = v.x;
            As[(kv + 1) * 64 + row] = v.y;
            As[(kv + 2) * 64 + row] = v.z;
            As[(kv + 3) * 64 + row] = v.w;
        }
        // load B tile (128 k x 128 n)
#pragma unroll
        for (int i = 0; i < 16; i++) {
            int idx = tid + i * 256;       // 0..4095
            int kr = idx >> 5;             // 0..127
            int nv = (idx & 31) << 2;      // 0..124
            *(float4*)(Bs + kr * 128 + nv) =
                *(const float4*)(B + (size_t)(kc + kr) * Ntot + n0 + nv);
        }
        __syncthreads();

#pragma unroll 16
        for (int k = 0; k < 128; k++) {
            float4 a  = *(const float4*)(As + k * 64 + ty * 4);
            float4 b0 = *(const float4*)(Bs + k * 128 + tx * 4);
            float4 b1 = *(const float4*)(Bs + k * 128 + 64 + tx * 4);
            float av[4] = {a.x, a.y, a.z, a.w};
            float bv[8] = {b0.x, b0.y, b0.z, b0.w, b1.x, b1.y, b1.z, b1.w};
#pragma unroll
            for (int r = 0; r < 4; r++)
#pragma unroll
                for (int c = 0; c < 8; c++) acc[r][c] = fmaf(av[r], bv[c], acc[r][c]);
        }
        __syncthreads();
    }

    // epilogue: thread covers cols {n0+tx*4..+3} and {n0+64+tx*4..+3}
#pragma unroll
    for (int r = 0; r < 4; r++) {
        int row = m0 + ty * 4 + r;
        if (row >= M) continue;
#pragma unroll
        for (int h = 0; h < 2; h++) {
            int col = n0 + h * 64 + tx * 4;
            float o0 = acc[r][h * 4 + 0], o1 = acc[r][h * 4 + 1];
            float o2 = acc[r][h * 4 + 2], o3 = acc[r][h * 4 + 3];
            if (EPI == 1) {
                float4 bb = *(const float4*)(bias + col);
                float4 rr = *(const float4*)(R + (size_t)row * Ntot + col);
                o0 += bb.x + rr.x; o1 += bb.y + rr.y;
                o2 += bb.z + rr.z; o3 += bb.w + rr.w;
            } else if (EPI == 2) {
                o0 = o0 / (1.0f + expf(-o0));
                o1 = o1 / (1.0f + expf(-o1));
                o2 = o2 / (1.0f + expf(-o2));
                o3 = o3 / (1.0f + expf(-o3));
            } else if (EPI == 3) {
                float4 rr = *(const float4*)(R + (size_t)row * Ntot + col);
                o0 += rr.x; o1 += rr.y; o2 += rr.z; o3 += rr.w;
            }
            float4 ov = make_float4(o0, o1, o2, o3);
            *(float4*)(C + (size_t)row * Ntot + col) = ov;
        }
    }
}

// ---------------- per-edge attention: one warp per edge ----------------
// reads Q,K,V (L2-resident), PE; writes e_attn (in place over PE);
// atomically accumulates wV[dst], z[dst].
__global__ void edge_kernel(const float* __restrict__ Q, const float* __restrict__ K,
                            const float* __restrict__ V, float* __restrict__ PE,
                            const int* __restrict__ eidx, float* __restrict__ wV,
                            float* __restrict__ z, int E) {
    int e = blockIdx.x * 8 + (threadIdx.x >> 5);
    if (e >= E) return;
    int lane = threadIdx.x & 31;
    int src = eidx[e];
    int dst = eidx[E + e];
    int i = lane * 4;
    float4 kv = *(const float4*)(K + (size_t)src * 128 + i);
    float4 qv = *(const float4*)(Q + (size_t)dst * 128 + i);
    float4 pe = *(const float4*)(PE + (size_t)e * 128 + i);
    const float sc = 0.25f;  // 1/sqrt(16)
    float s0 = fminf(fmaxf(kv.x * qv.x * sc, -5.0f), 5.0f) * pe.x;
    float s1 = fminf(fmaxf(kv.y * qv.y * sc, -5.0f), 5.0f) * pe.y;
    float s2 = fminf(fmaxf(kv.z * qv.z * sc, -5.0f), 5.0f) * pe.z;
    float s3 = fminf(fmaxf(kv.w * qv.w * sc, -5.0f), 5.0f) * pe.w;
    *(float4*)(PE + (size_t)e * 128 + i) = make_float4(s0, s1, s2, s3);

    // head = lane>>2 covers elements [16h,16h+16): sum over the 4 lanes of the head
    float hs = s0 + s1 + s2 + s3;
    hs += __shfl_xor_sync(0xffffffffu, hs, 1);
    hs += __shfl_xor_sync(0xffffffffu, hs, 2);
    float w = expf(fminf(fmaxf(hs, -5.0f), 5.0f));

    float4 vv = *(const float4*)(V + (size_t)src * 128 + i);
    float* base = wV + (size_t)dst * 128 + i;
    atomicAdd(base + 0, vv.x * w);
    atomicAdd(base + 1, vv.y * w);
    atomicAdd(base + 2, vv.z * w);
    atomicAdd(base + 3, vv.w * w);
    if ((lane & 3) == 0) atomicAdd(z + (size_t)dst * 8 + (lane >> 2), w);
}

// ---------------- h_attn = wV / (z + 1e-6) ----------------
__global__ void hattn_kernel(const float* __restrict__ wV, const float* __restrict__ z,
                             float* __restrict__ out, int N) {
    int idx = blockIdx.x * 256 + threadIdx.x;
    if (idx >= N * 128) return;
    int n = idx >> 7;
    int h = (idx >> 4) & 7;
    out[idx] = wV[idx] / (z[(size_t)n * 8 + h] + 1e-6f);
}

// ---------------- launch ----------------
extern "C" void kernel_launch(void* const* d_in, const int* in_sizes, int n_in,
                              void* d_out, int out_size) {
    const float* node = (const float*)d_in[0];
    const float* edge = (const float*)d_in[1];
    const int*   eidx = (const int*)d_in[2];
    const float* Wq   = (const float*)d_in[3];
    const float* Wk   = (const float*)d_in[4];
    const float* Wv   = (const float*)d_in[5];
    const float* We   = (const float*)d_in[6];
    const float* Wo_n = (const float*)d_in[7];
    const float* bo_n = (const float*)d_in[8];
    const float* Wo_e = (const float*)d_in[9];
    const float* bo_e = (const float*)d_in[10];
    const float* W1n  = (const float*)d_in[11];
    const float* W2n  = (const float*)d_in[12];
    const float* W1e  = (const float*)d_in[13];
    const float* W2e  = (const float*)d_in[14];
    const float* g1n  = (const float*)d_in[15];
    const float* b1n  = (const float*)d_in[16];
    const float* g1e  = (const float*)d_in[17];
    const float* b1e  = (const float*)d_in[18];
    const float* g2n  = (const float*)d_in[19];
    const float* b2n  = (const float*)d_in[20];
    const float* g2e  = (const float*)d_in[21];
    const float* b2e  = (const float*)d_in[22];

    const int N = in_sizes[0] / 128;
    const int E = in_sizes[1] / 128;
    float* out = (float*)d_out;

    float *hln, *eln, *Q, *Kb, *Vb, *PE, *wV, *z, *h2, *e2, *tn, *te;
    cudaGetSymbolAddress((void**)&hln, g_hln);
    cudaGetSymbolAddress((void**)&eln, g_eln);
    cudaGetSymbolAddress((void**)&Q,   g_Q);
    cudaGetSymbolAddress((void**)&Kb,  g_Kb);
    cudaGetSymbolAddress((void**)&Vb,  g_Vb);
    cudaGetSymbolAddress((void**)&PE,  g_PE);
    cudaGetSymbolAddress((void**)&wV,  g_wV);
    cudaGetSymbolAddress((void**)&z,   g_z);
    cudaGetSymbolAddress((void**)&h2,  g_h2);
    cudaGetSymbolAddress((void**)&e2,  g_e2);
    cudaGetSymbolAddress((void**)&tn,  g_tn);
    cudaGetSymbolAddress((void**)&te,  g_te);

    const int SMEM = (128 * 64 + 128 * 128) * 4;  // 96 KB dynamic
    cudaFuncSetAttribute(gemm_kernel<0>, cudaFuncAttributeMaxDynamicSharedMemorySize, SMEM);
    cudaFuncSetAttribute(gemm_kernel<1>, cudaFuncAttributeMaxDynamicSharedMemorySize, SMEM);
    cudaFuncSetAttribute(gemm_kernel<2>, cudaFuncAttributeMaxDynamicSharedMemorySize, SMEM);
    cudaFuncSetAttribute(gemm_kernel<3>, cudaFuncAttributeMaxDynamicSharedMemorySize, SMEM);

    const int MtN = (N + 63) / 64;
    const int MtE = (E + 63) / 64;

    // 1) pre-norms
    ln_kernel<<<(N + 7) / 8, 256>>>(node, g1n, b1n, hln, N);
    ln_kernel<<<(E + 7) / 8, 256>>>(edge, g1e, b1e, eln, E);

    // 2) projections
    gemm_kernel<0><<<dim3(MtN, 1), 256, SMEM>>>(hln, Wq, Q,  nullptr, nullptr, N, 128, 128);
    gemm_kernel<0><<<dim3(MtN, 1), 256, SMEM>>>(hln, Wk, Kb, nullptr, nullptr, N, 128, 128);
    gemm_kernel<0><<<dim3(MtN, 1), 256, SMEM>>>(hln, Wv, Vb, nullptr, nullptr, N, 128, 128);
    gemm_kernel<0><<<dim3(MtE, 1), 256, SMEM>>>(eln, We, PE, nullptr, nullptr, E, 128, 128);

    // 3) zero accumulators, per-edge attention + segment aggregation
    zero_kernel<<<4096, 256>>>(wV, (size_t)N * 128);
    zero_kernel<<<256, 256>>>(z, (size_t)N * 8);
    edge_kernel<<<(E + 7) / 8, 256>>>(Q, Kb, Vb, PE, eidx, wV, z, E);

    // 4) h_attn normalize (reuse hln)
    hattn_kernel<<<(N * 128 + 255) / 256, 256>>>(wV, z, hln, N);

    // 5) output projections + residuals
    gemm_kernel<1><<<dim3(MtN, 1), 256, SMEM>>>(hln, Wo_n, h2, bo_n, node, N, 128, 128);
    gemm_kernel<1><<<dim3(MtE, 1), 256, SMEM>>>(PE,  Wo_e, e2, bo_e, edge, E, 128, 128);

    // 6) norm2
    ln_kernel<<<(N + 7) / 8, 256>>>(h2, g2n, b2n, hln, N);
    ln_kernel<<<(E + 7) / 8, 256>>>(e2, g2e, b2e, eln, E);

    // 7) FFN: silu(x @ W1) @ W2 + residual -> final outputs
    gemm_kernel<2><<<dim3(MtN, 2), 256, SMEM>>>(hln, W1n, tn, nullptr, nullptr, N, 128, 256);
    gemm_kernel<3><<<dim3(MtN, 1), 256, SMEM>>>(tn, W2n, out, nullptr, h2, N, 256, 128);
    gemm_kernel<2><<<dim3(MtE, 2), 256, SMEM>>>(eln, W1e, te, nullptr, nullptr, E, 128, 256);
    gemm_kernel<3><<<dim3(MtE, 1), 256, SMEM>>>(te, W2e, out + (size_t)N * 128, nullptr, e2,
                                                E, 256, 128);
}

// round 3
// speedup vs baseline: 1.8747x; 1.8747x over previous
#include <cuda_runtime.h>
#include <cuda_bf16.h>
#include <math.h>
#include <stdint.h>

// ================= scratch (device globals) =================
#define NMAX 50000
#define EMAX 400000

__device__ float g_hln[(size_t)NMAX * 128];
__device__ float g_eln[(size_t)EMAX * 128];
__device__ float g_Q  [(size_t)NMAX * 128];
__device__ float g_Kb [(size_t)NMAX * 128];
__device__ float g_Vb [(size_t)NMAX * 128];
__device__ float g_PE [(size_t)EMAX * 128];
__device__ float g_wV [(size_t)NMAX * 128];
__device__ float g_z  [(size_t)NMAX * 8];
__device__ float g_h2 [(size_t)NMAX * 128];
__device__ float g_e2 [(size_t)EMAX * 128];
__device__ float g_tn [(size_t)NMAX * 256];
__device__ float g_te [(size_t)EMAX * 256];
// weight images: [n][k] bf16, k padded by 8; 10 slots x 80KB, hi and lo
__device__ char g_wimgh[10][81920];
__device__ char g_wimgl[10][81920];

// ================= mma.sync bf16 helper =================
__device__ __forceinline__ void mma_bf16(float* c, const uint32_t* a, const uint32_t* b) {
    asm volatile(
        "mma.sync.aligned.m16n8k16.row.col.f32.bf16.bf16.f32 "
        "{%0,%1,%2,%3}, {%4,%5,%6,%7}, {%8,%9}, {%0,%1,%2,%3};"
        : "+f"(c[0]), "+f"(c[1]), "+f"(c[2]), "+f"(c[3])
        : "r"(a[0]), "r"(a[1]), "r"(a[2]), "r"(a[3]), "r"(b[0]), "r"(b[1]));
}

// ================= LayerNorm (one warp per 128-row) =================
__global__ void ln_kernel(const float* __restrict__ x, const float* __restrict__ g,
                          const float* __restrict__ b, float* __restrict__ y, int rows) {
    int row = blockIdx.x * 8 + (threadIdx.x >> 5);
    if (row >= rows) return;
    int lane = threadIdx.x & 31;
    const float4 v = *(const float4*)(x + (size_t)row * 128 + lane * 4);
    float s = v.x + v.y + v.z + v.w;
#pragma unroll
    for (int o = 16; o; o >>= 1) s += __shfl_xor_sync(0xffffffffu, s, o);
    float mu = s * 0.0078125f;
    float d0 = v.x - mu, d1 = v.y - mu, d2 = v.z - mu, d3 = v.w - mu;
    float q = d0 * d0 + d1 * d1 + d2 * d2 + d3 * d3;
#pragma unroll
    for (int o = 16; o; o >>= 1) q += __shfl_xor_sync(0xffffffffu, q, o);
    float inv = rsqrtf(q * 0.0078125f + 1e-5f);
    float4 gg = *(const float4*)(g + lane * 4);
    float4 bb = *(const float4*)(b + lane * 4);
    float4 o;
    o.x = d0 * inv * gg.x + bb.x;
    o.y = d1 * inv * gg.y + bb.y;
    o.z = d2 * inv * gg.z + bb.z;
    o.w = d3 * inv * gg.w + bb.w;
    *(float4*)(y + (size_t)row * 128 + lane * 4) = o;
}

__global__ void zero_kernel(float* __restrict__ a, size_t n) {
    size_t i = (size_t)blockIdx.x * blockDim.x + threadIdx.x;
    size_t st = (size_t)gridDim.x * blockDim.x;
    for (; i < n; i += st) a[i] = 0.0f;
}

// ====== weight prep: W[K,N] row-major -> images [n][k] bf16 hi/lo, k-stride K+8 ======
__global__ void prep_weights(const float* __restrict__ W, char* __restrict__ ih,
                             char* __restrict__ il, int K, int N) {
    int idx = blockIdx.x * 256 + threadIdx.x;
    if (idx >= K * N) return;
    int k = idx / N, n = idx % N;
    float w = W[idx];
    __nv_bfloat16 hi = __float2bfloat16(w);
    __nv_bfloat16 lo = __float2bfloat16(w - __bfloat162float(hi));
    size_t off = ((size_t)n * (K + 8) + k) * 2;
    *(unsigned short*)(ih + off) = __bfloat16_as_ushort(hi);
    *(unsigned short*)(il + off) = __bfloat16_as_ushort(lo);
}

// ================= HMMA GEMM: C[M,ldc] tile = A[M,K] @ W[K,*] (bf16x3 split) =========
// CTA 128x128, 8 warps (2m x 4n), warp tile 64x32. K chunked by 128.
// EPI: 0 none, 1 +bias+residual, 2 silu, 3 +residual
#define SMS 136   // smem k-stride in bf16 elements
#define SMSB 272  // bytes
template <int EPI>
__global__ __launch_bounds__(256, 1)
void mma_gemm(const float* __restrict__ A, const char* __restrict__ Bh,
              const char* __restrict__ Bl, float* __restrict__ C,
              const float* __restrict__ bias, const float* __restrict__ Rr,
              int M, int K, int ldc) {
    extern __shared__ char smem[];
    char* a_hi = smem;
    char* a_lo = a_hi + 128 * SMSB;
    char* b_hi = a_lo + 128 * SMSB;
    char* b_lo = b_hi + 128 * SMSB;

    const int tid = threadIdx.x, wid = tid >> 5, lane = tid & 31;
    const int wm = wid >> 2, wn = wid & 3;        // 2 x 4 warp grid
    const int q = lane >> 2, t2 = (lane & 3) * 2; // fragment row/col within tile
    const int m0 = blockIdx.x * 128;
    const int n_base = blockIdx.y * 128;
    const int Kp2 = (K + 8) * 2;  // image row bytes

    float acc[4][4][4];
#pragma unroll
    for (int mt = 0; mt < 4; mt++)
#pragma unroll
        for (int nt = 0; nt < 4; nt++)
#pragma unroll
            for (int j = 0; j < 4; j++) acc[mt][nt][j] = 0.0f;

    const int nchunks = K >> 7;
    for (int c = 0; c < nchunks; c++) {
        if (c > 0) __syncthreads();
        // ---- A chunk: 128 rows x 128 k fp32 -> bf16 hi/lo in smem ----
#pragma unroll 4
        for (int i = tid; i < 128 * 32; i += 256) {
            int row = i >> 5;
            int k4 = (i & 31) << 2;
            float4 v = make_float4(0.f, 0.f, 0.f, 0.f);
            if (m0 + row < M) v = *(const float4*)(A + (size_t)(m0 + row) * K + c * 128 + k4);
            __nv_bfloat16 h0 = __float2bfloat16(v.x), h1 = __float2bfloat16(v.y);
            __nv_bfloat16 h2 = __float2bfloat16(v.z), h3 = __float2bfloat16(v.w);
            __nv_bfloat16 l0 = __float2bfloat16(v.x - __bfloat162float(h0));
            __nv_bfloat16 l1 = __float2bfloat16(v.y - __bfloat162float(h1));
            __nv_bfloat16 l2 = __float2bfloat16(v.z - __bfloat162float(h2));
            __nv_bfloat16 l3 = __float2bfloat16(v.w - __bfloat162float(h3));
            uint2 H, L;
            H.x = (uint32_t)__bfloat16_as_ushort(h0) | ((uint32_t)__bfloat16_as_ushort(h1) << 16);
            H.y = (uint32_t)__bfloat16_as_ushort(h2) | ((uint32_t)__bfloat16_as_ushort(h3) << 16);
            L.x = (uint32_t)__bfloat16_as_ushort(l0) | ((uint32_t)__bfloat16_as_ushort(l1) << 16);
            L.y = (uint32_t)__bfloat16_as_ushort(l2) | ((uint32_t)__bfloat16_as_ushort(l3) << 16);
            int off = row * SMSB + k4 * 2;
            *(uint2*)(a_hi + off) = H;
            *(uint2*)(a_lo + off) = L;
        }
        // ---- B chunk: copy image rows [n_base..n_base+128), k bytes [c*256, +256) ----
#pragma unroll 4
        for (int i = tid; i < 128 * 16; i += 256) {
            int n = i >> 4, j = i & 15;
            size_t src = (size_t)(n_base + n) * Kp2 + c * 256 + j * 16;
            int dst = n * SMSB + j * 16;
            *(uint4*)(b_hi + dst) = *(const uint4*)(Bh + src);
            *(uint4*)(b_lo + dst) = *(const uint4*)(Bl + src);
        }
        __syncthreads();

        // ---- compute: 8 k16-steps ----
#pragma unroll
        for (int ks = 0; ks < 8; ks++) {
            uint32_t ah[4][4], al[4][4], bh[4][2], bl[4][2];
#pragma unroll
            for (int mt = 0; mt < 4; mt++) {
                int off = (wm * 64 + mt * 16 + q) * SMSB + (ks * 16 + t2) * 2;
                ah[mt][0] = *(const uint32_t*)(a_hi + off);
                ah[mt][1] = *(const uint32_t*)(a_hi + off + 8 * SMSB);
                ah[mt][2] = *(const uint32_t*)(a_hi + off + 16);
                ah[mt][3] = *(const uint32_t*)(a_hi + off + 8 * SMSB + 16);
                al[mt][0] = *(const uint32_t*)(a_lo + off);
                al[mt][1] = *(const uint32_t*)(a_lo + off + 8 * SMSB);
                al[mt][2] = *(const uint32_t*)(a_lo + off + 16);
                al[mt][3] = *(const uint32_t*)(a_lo + off + 8 * SMSB + 16);
            }
#pragma unroll
            for (int nt = 0; nt < 4; nt++) {
                int off = (wn * 32 + nt * 8 + q) * SMSB + (ks * 16 + t2) * 2;
                bh[nt][0] = *(const uint32_t*)(b_hi + off);
                bh[nt][1] = *(const uint32_t*)(b_hi + off + 16);
                bl[nt][0] = *(const uint32_t*)(b_lo + off);
                bl[nt][1] = *(const uint32_t*)(b_lo + off + 16);
            }
#pragma unroll
            for (int mt = 0; mt < 4; mt++)
#pragma unroll
                for (int nt = 0; nt < 4; nt++) {
                    mma_bf16(acc[mt][nt], ah[mt], bh[nt]);
                    mma_bf16(acc[mt][nt], ah[mt], bl[nt]);
                    mma_bf16(acc[mt][nt], al[mt], bh[nt]);
                }
        }
    }

    // ---- epilogue ----
#pragma unroll
    for (int mt = 0; mt < 4; mt++) {
#pragma unroll
        for (int half = 0; half < 2; half++) {
            int row = m0 + wm * 64 + mt * 16 + q + half * 8;
            if (row >= M) continue;
#pragma unroll
            for (int nt = 0; nt < 4; nt++) {
                int col = n_base + wn * 32 + nt * 8 + t2;
                float o0 = acc[mt][nt][half * 2 + 0];
                float o1 = acc[mt][nt][half * 2 + 1];
                if (EPI == 1) {
                    float2 bb = *(const float2*)(bias + col);
                    float2 rr = *(const float2*)(Rr + (size_t)row * ldc + col);
                    o0 += bb.x + rr.x;
                    o1 += bb.y + rr.y;
                } else if (EPI == 2) {
                    o0 = o0 / (1.0f + expf(-o0));
                    o1 = o1 / (1.0f + expf(-o1));
                } else if (EPI == 3) {
                    float2 rr = *(const float2*)(Rr + (size_t)row * ldc + col);
                    o0 += rr.x;
                    o1 += rr.y;
                }
                *(float2*)(C + (size_t)row * ldc + col) = make_float2(o0, o1);
            }
        }
    }
}

// ================= per-edge attention (one warp per edge) =================
__global__ void edge_kernel(const float* __restrict__ Q, const float* __restrict__ K,
                            const float* __restrict__ V, float* __restrict__ PE,
                            const int* __restrict__ eidx, float* __restrict__ wV,
                            float* __restrict__ z, int E) {
    int e = blockIdx.x * 8 + (threadIdx.x >> 5);
    if (e >= E) return;
    int lane = threadIdx.x & 31;
    int src = eidx[e];
    int dst = eidx[E + e];
    int i = lane * 4;
    float4 kv = *(const float4*)(K + (size_t)src * 128 + i);
    float4 qv = *(const float4*)(Q + (size_t)dst * 128 + i);
    float4 pe = *(const float4*)(PE + (size_t)e * 128 + i);
    const float sc = 0.25f;
    float s0 = fminf(fmaxf(kv.x * qv.x * sc, -5.0f), 5.0f) * pe.x;
    float s1 = fminf(fmaxf(kv.y * qv.y * sc, -5.0f), 5.0f) * pe.y;
    float s2 = fminf(fmaxf(kv.z * qv.z * sc, -5.0f), 5.0f) * pe.z;
    float s3 = fminf(fmaxf(kv.w * qv.w * sc, -5.0f), 5.0f) * pe.w;
    *(float4*)(PE + (size_t)e * 128 + i) = make_float4(s0, s1, s2, s3);

    float hs = s0 + s1 + s2 + s3;
    hs += __shfl_xor_sync(0xffffffffu, hs, 1);
    hs += __shfl_xor_sync(0xffffffffu, hs, 2);
    float w = expf(fminf(fmaxf(hs, -5.0f), 5.0f));

    float4 vv = *(const float4*)(V + (size_t)src * 128 + i);
    float* base = wV + (size_t)dst * 128 + i;
    atomicAdd(base + 0, vv.x * w);
    atomicAdd(base + 1, vv.y * w);
    atomicAdd(base + 2, vv.z * w);
    atomicAdd(base + 3, vv.w * w);
    if ((lane & 3) == 0) atomicAdd(z + (size_t)dst * 8 + (lane >> 2), w);
}

__global__ void hattn_kernel(const float* __restrict__ wV, const float* __restrict__ z,
                             float* __restrict__ out, int N) {
    int idx = blockIdx.x * 256 + threadIdx.x;
    if (idx >= N * 128) return;
    int n = idx >> 7;
    int h = (idx >> 4) & 7;
    out[idx] = wV[idx] / (z[(size_t)n * 8 + h] + 1e-6f);
}

// ================= launch =================
extern "C" void kernel_launch(void* const* d_in, const int* in_sizes, int n_in,
                              void* d_out, int out_size) {
    const float* node = (const float*)d_in[0];
    const float* edge = (const float*)d_in[1];
    const int*   eidx = (const int*)d_in[2];
    const float* Wq = (const float*)d_in[3];
    const float* Wk = (const float*)d_in[4];
    const float* Wv = (const float*)d_in[5];
    const float* We = (const float*)d_in[6];
    const float* Wo_n = (const float*)d_in[7];
    const float* bo_n = (const float*)d_in[8];
    const float* Wo_e = (const float*)d_in[9];
    const float* bo_e = (const float*)d_in[10];
    const float* W1n = (const float*)d_in[11];
    const float* W2n = (const float*)d_in[12];
    const float* W1e = (const float*)d_in[13];
    const float* W2e = (const float*)d_in[14];
    const float* g1n = (const float*)d_in[15];
    const float* b1n = (const float*)d_in[16];
    const float* g1e = (const float*)d_in[17];
    const float* b1e = (const float*)d_in[18];
    const float* g2n = (const float*)d_in[19];
    const float* b2n = (const float*)d_in[20];
    const float* g2e = (const float*)d_in[21];
    const float* b2e = (const float*)d_in[22];

    const int N = in_sizes[0] / 128;
    const int E = in_sizes[1] / 128;
    float* out = (float*)d_out;

    float *hln, *eln, *Q, *Kb, *Vb, *PE, *wV, *z, *h2, *e2, *tn, *te;
    char *wih, *wil;
    cudaGetSymbolAddress((void**)&hln, g_hln);
    cudaGetSymbolAddress((void**)&eln, g_eln);
    cudaGetSymbolAddress((void**)&Q, g_Q);
    cudaGetSymbolAddress((void**)&Kb, g_Kb);
    cudaGetSymbolAddress((void**)&Vb, g_Vb);
    cudaGetSymbolAddress((void**)&PE, g_PE);
    cudaGetSymbolAddress((void**)&wV, g_wV);
    cudaGetSymbolAddress((void**)&z, g_z);
    cudaGetSymbolAddress((void**)&h2, g_h2);
    cudaGetSymbolAddress((void**)&e2, g_e2);
    cudaGetSymbolAddress((void**)&tn, g_tn);
    cudaGetSymbolAddress((void**)&te, g_te);
    cudaGetSymbolAddress((void**)&wih, g_wimgh);
    cudaGetSymbolAddress((void**)&wil, g_wimgl);

    auto IH = [&](int i) { return wih + (size_t)i * 81920; };
    auto IL = [&](int i) { return wil + (size_t)i * 81920; };

    const int SMEM = 4 * 128 * SMSB;  // 139264 B
    cudaFuncSetAttribute(mma_gemm<0>, cudaFuncAttributeMaxDynamicSharedMemorySize, SMEM);
    cudaFuncSetAttribute(mma_gemm<1>, cudaFuncAttributeMaxDynamicSharedMemorySize, SMEM);
    cudaFuncSetAttribute(mma_gemm<2>, cudaFuncAttributeMaxDynamicSharedMemorySize, SMEM);
    cudaFuncSetAttribute(mma_gemm<3>, cudaFuncAttributeMaxDynamicSharedMemorySize, SMEM);

    const int TtN = (N + 127) / 128;
    const int TtE = (E + 127) / 128;

    // 0) weight images
    prep_weights<<<64, 256>>>(Wq, IH(0), IL(0), 128, 128);
    prep_weights<<<64, 256>>>(Wk, IH(1), IL(1), 128, 128);
    prep_weights<<<64, 256>>>(Wv, IH(2), IL(2), 128, 128);
    prep_weights<<<64, 256>>>(We, IH(3), IL(3), 128, 128);
    prep_weights<<<64, 256>>>(Wo_n, IH(4), IL(4), 128, 128);
    prep_weights<<<64, 256>>>(Wo_e, IH(5), IL(5), 128, 128);
    prep_weights<<<128, 256>>>(W1n, IH(6), IL(6), 128, 256);
    prep_weights<<<128, 256>>>(W1e, IH(7), IL(7), 128, 256);
    prep_weights<<<128, 256>>>(W2n, IH(8), IL(8), 256, 128);
    prep_weights<<<128, 256>>>(W2e, IH(9), IL(9), 256, 128);

    // 1) pre-norms
    ln_kernel<<<(N + 7) / 8, 256>>>(node, g1n, b1n, hln, N);
    ln_kernel<<<(E + 7) / 8, 256>>>(edge, g1e, b1e, eln, E);

    // 2) projections
    mma_gemm<0><<<dim3(TtN, 1), 256, SMEM>>>(hln, IH(0), IL(0), Q, nullptr, nullptr, N, 128, 128);
    mma_gemm<0><<<dim3(TtN, 1), 256, SMEM>>>(hln, IH(1), IL(1), Kb, nullptr, nullptr, N, 128, 128);
    mma_gemm<0><<<dim3(TtN, 1), 256, SMEM>>>(hln, IH(2), IL(2), Vb, nullptr, nullptr, N, 128, 128);
    mma_gemm<0><<<dim3(TtE, 1), 256, SMEM>>>(eln, IH(3), IL(3), PE, nullptr, nullptr, E, 128, 128);

    // 3) attention aggregation
    zero_kernel<<<4096, 256>>>(wV, (size_t)N * 128);
    zero_kernel<<<256, 256>>>(z, (size_t)N * 8);
    edge_kernel<<<(E + 7) / 8, 256>>>(Q, Kb, Vb, PE, eidx, wV, z, E);
    hattn_kernel<<<(N * 128 + 255) / 256, 256>>>(wV, z, hln, N);

    // 4) output projections + residuals
    mma_gemm<1><<<dim3(TtN, 1), 256, SMEM>>>(hln, IH(4), IL(4), h2, bo_n, node, N, 128, 128);
    mma_gemm<1><<<dim3(TtE, 1), 256, SMEM>>>(PE, IH(5), IL(5), e2, bo_e, edge, E, 128, 128);

    // 5) norm2
    ln_kernel<<<(N + 7) / 8, 256>>>(h2, g2n, b2n, hln, N);
    ln_kernel<<<(E + 7) / 8, 256>>>(e2, g2e, b2e, eln, E);

    // 6) FFN
    mma_gemm<2><<<dim3(TtN, 2), 256, SMEM>>>(hln, IH(6), IL(6), tn, nullptr, nullptr, N, 128, 256);
    mma_gemm<3><<<dim3(TtN, 1), 256, SMEM>>>(tn, IH(8), IL(8), out, nullptr, h2, N, 256, 128);
    mma_gemm<2><<<dim3(TtE, 2), 256, SMEM>>>(eln, IH(7), IL(7), te, nullptr, nullptr, E, 128, 256);
    mma_gemm<3><<<dim3(TtE, 1), 256, SMEM>>>(te, IH(9), IL(9), out + (size_t)N * 128, nullptr, e2,
                                             E, 256, 128);
}

// round 4
// speedup vs baseline: 2.2522x; 1.2014x over previous
#include <cuda_runtime.h>
#include <cuda_bf16.h>
#include <math.h>
#include <stdint.h>

// ================= scratch (device globals) =================
#define NMAX 50000
#define EMAX 400000

__device__ float g_Q  [(size_t)NMAX * 128];
__device__ float g_Kb [(size_t)NMAX * 128];
__device__ float g_Vb [(size_t)NMAX * 128];
__device__ float g_PE [(size_t)EMAX * 128];
__device__ float g_wV [(size_t)NMAX * 128];
__device__ float g_z  [(size_t)NMAX * 8];
__device__ float g_h2 [(size_t)NMAX * 128];
__device__ float g_e2 [(size_t)EMAX * 128];
// weight images: [n][k] bf16, k padded by 8; 10 slots x 80KB, hi and lo
__device__ char g_wimgh[10][81920];
__device__ char g_wimgl[10][81920];

#define SMSB 272  // smem k-stride in bytes (136 bf16)

// ================= mma.sync bf16 helper =================
__device__ __forceinline__ void mma_bf16(float* c, const uint32_t* a, const uint32_t* b) {
    asm volatile(
        "mma.sync.aligned.m16n8k16.row.col.f32.bf16.bf16.f32 "
        "{%0,%1,%2,%3}, {%4,%5,%6,%7}, {%8,%9}, {%0,%1,%2,%3};"
        : "+f"(c[0]), "+f"(c[1]), "+f"(c[2]), "+f"(c[3])
        : "r"(a[0]), "r"(a[1]), "r"(a[2]), "r"(a[3]), "r"(b[0]), "r"(b[1]));
}

// 128x128x128 bf16x3 tile compute; 8 warps in 2x4; acc accumulates.
__device__ __forceinline__ void compute_tile(float (&acc)[4][4][4],
                                             const char* a_hi, const char* a_lo,
                                             const char* b_hi, const char* b_lo,
                                             int wm, int wn, int q, int t2) {
#pragma unroll
    for (int ks = 0; ks < 8; ks++) {
        uint32_t ah[4][4], al[4][4], bh[4][2], bl[4][2];
#pragma unroll
        for (int mt = 0; mt < 4; mt++) {
            int off = (wm * 64 + mt * 16 + q) * SMSB + (ks * 16 + t2) * 2;
            ah[mt][0] = *(const uint32_t*)(a_hi + off);
            ah[mt][1] = *(const uint32_t*)(a_hi + off + 8 * SMSB);
            ah[mt][2] = *(const uint32_t*)(a_hi + off + 16);
            ah[mt][3] = *(const uint32_t*)(a_hi + off + 8 * SMSB + 16);
            al[mt][0] = *(const uint32_t*)(a_lo + off);
            al[mt][1] = *(const uint32_t*)(a_lo + off + 8 * SMSB);
            al[mt][2] = *(const uint32_t*)(a_lo + off + 16);
            al[mt][3] = *(const uint32_t*)(a_lo + off + 8 * SMSB + 16);
        }
#pragma unroll
        for (int nt = 0; nt < 4; nt++) {
            int off = (wn * 32 + nt * 8 + q) * SMSB + (ks * 16 + t2) * 2;
            bh[nt][0] = *(const uint32_t*)(b_hi + off);
            bh[nt][1] = *(const uint32_t*)(b_hi + off + 16);
            bl[nt][0] = *(const uint32_t*)(b_lo + off);
            bl[nt][1] = *(const uint32_t*)(b_lo + off + 16);
        }
#pragma unroll
        for (int mt = 0; mt < 4; mt++)
#pragma unroll
            for (int nt = 0; nt < 4; nt++) {
                mma_bf16(acc[mt][nt], ah[mt], bh[nt]);
                mma_bf16(acc[mt][nt], ah[mt], bl[nt]);
                mma_bf16(acc[mt][nt], al[mt], bh[nt]);
            }
    }
}

// split fp32 -> bf16 hi/lo packed pair
__device__ __forceinline__ void split2(float x, float y, uint32_t& H, uint32_t& L) {
    __nv_bfloat16 hx = __float2bfloat16(x), hy = __float2bfloat16(y);
    __nv_bfloat16 lx = __float2bfloat16(x - __bfloat162float(hx));
    __nv_bfloat16 ly = __float2bfloat16(y - __bfloat162float(hy));
    H = (uint32_t)__bfloat16_as_ushort(hx) | ((uint32_t)__bfloat16_as_ushort(hy) << 16);
    L = (uint32_t)__bfloat16_as_ushort(lx) | ((uint32_t)__bfloat16_as_ushort(ly) << 16);
}

// A-load (rows of 128 fp32), optional transform. ALOAD: 0 plain, 1 LN(P1=g,P2=b), 2 div-by-z(P1=z)
template <int ALOAD>
__device__ __forceinline__ void load_A(const float* __restrict__ A,
                                       const float* __restrict__ P1,
                                       const float* __restrict__ P2,
                                       int M, int m0, char* a_hi, char* a_lo, int tid) {
    const int lane = tid & 31;
    float4 gg, bb;
    if (ALOAD == 1) {
        gg = *(const float4*)(P1 + lane * 4);
        bb = *(const float4*)(P2 + lane * 4);
    }
#pragma unroll 4
    for (int i = tid; i < 4096; i += 256) {
        int row = i >> 5;  // one row per warp per iteration (lane = i&31)
        float4 v = make_float4(0.f, 0.f, 0.f, 0.f);
        bool valid = (m0 + row < M);
        if (valid) v = *(const float4*)(A + (size_t)(m0 + row) * 128 + lane * 4);
        if (ALOAD == 1) {
            float s = v.x + v.y + v.z + v.w;
#pragma unroll
            for (int o = 16; o; o >>= 1) s += __shfl_xor_sync(0xffffffffu, s, o);
            float mu = s * 0.0078125f;
            float d0 = v.x - mu, d1 = v.y - mu, d2 = v.z - mu, d3 = v.w - mu;
            float qq = d0 * d0 + d1 * d1 + d2 * d2 + d3 * d3;
#pragma unroll
            for (int o = 16; o; o >>= 1) qq += __shfl_xor_sync(0xffffffffu, qq, o);
            float inv = rsqrtf(qq * 0.0078125f + 1e-5f);
            v.x = d0 * inv * gg.x + bb.x;
            v.y = d1 * inv * gg.y + bb.y;
            v.z = d2 * inv * gg.z + bb.z;
            v.w = d3 * inv * gg.w + bb.w;
        } else if (ALOAD == 2) {
            float zz = valid ? P1[(size_t)(m0 + row) * 8 + (lane >> 2)] : 1.0f;
            float inv = 1.0f / (zz + 1e-6f);
            v.x *= inv; v.y *= inv; v.z *= inv; v.w *= inv;
        }
        uint2 H, L;
        split2(v.x, v.y, H.x, L.x);
        split2(v.z, v.w, H.y, L.y);
        int off = row * SMSB + lane * 8;
        *(uint2*)(a_hi + off) = H;
        *(uint2*)(a_lo + off) = L;
    }
}

// ================= unified HMMA GEMM (K=128): C = op(A) @ Wslot =================
// EPI: 0 none, 1 +bias+residual. grid.y selects B slot and C among C0/C1/C2.
template <int EPI, int ALOAD>
__global__ __launch_bounds__(256, 1)
void mma_gemm(const float* __restrict__ A, const float* __restrict__ P1,
              const float* __restrict__ P2, const char* __restrict__ BhBase,
              const char* __restrict__ BlBase, float* __restrict__ C0,
              float* __restrict__ C1, float* __restrict__ C2,
              const float* __restrict__ bias, const float* __restrict__ Rr, int M) {
    extern __shared__ char smem[];
    char* a_hi = smem;
    char* a_lo = a_hi + 128 * SMSB;
    char* b_hi = a_lo + 128 * SMSB;
    char* b_lo = b_hi + 128 * SMSB;

    const int tid = threadIdx.x, wid = tid >> 5, lane = tid & 31;
    const int wm = wid >> 2, wn = wid & 3;
    const int q = lane >> 2, t2 = (lane & 3) * 2;
    const int m0 = blockIdx.x * 128;
    const char* Bh = BhBase + (size_t)blockIdx.y * 81920;
    const char* Bl = BlBase + (size_t)blockIdx.y * 81920;
    float* C = (blockIdx.y == 0) ? C0 : (blockIdx.y == 1) ? C1 : C2;

    float acc[4][4][4];
#pragma unroll
    for (int mt = 0; mt < 4; mt++)
#pragma unroll
        for (int nt = 0; nt < 4; nt++)
#pragma unroll
            for (int j = 0; j < 4; j++) acc[mt][nt][j] = 0.0f;

    load_A<ALOAD>(A, P1, P2, M, m0, a_hi, a_lo, tid);
    // B: contiguous 128x272B image copy
#pragma unroll 4
    for (int i = tid * 16; i < 128 * SMSB; i += 256 * 16) {
        *(uint4*)(b_hi + i) = *(const uint4*)(Bh + i);
        *(uint4*)(b_lo + i) = *(const uint4*)(Bl + i);
    }
    __syncthreads();
    compute_tile(acc, a_hi, a_lo, b_hi, b_lo, wm, wn, q, t2);

#pragma unroll
    for (int mt = 0; mt < 4; mt++) {
#pragma unroll
        for (int half = 0; half < 2; half++) {
            int row = m0 + wm * 64 + mt * 16 + q + half * 8;
            if (row >= M) continue;
#pragma unroll
            for (int nt = 0; nt < 4; nt++) {
                int col = wn * 32 + nt * 8 + t2;
                float o0 = acc[mt][nt][half * 2 + 0];
                float o1 = acc[mt][nt][half * 2 + 1];
                if (EPI == 1) {
                    float2 bbv = *(const float2*)(bias + col);
                    float2 rr = *(const float2*)(Rr + (size_t)row * 128 + col);
                    o0 += bbv.x + rr.x;
                    o1 += bbv.y + rr.y;
                }
                *(float2*)(C + (size_t)row * 128 + col) = make_float2(o0, o1);
            }
        }
    }
}

// ============ fused FFN: out = x + silu(LN(x)@W1) @ W2, per 128-row tile ============
__global__ __launch_bounds__(256, 1)
void ffn_fused(const float* __restrict__ X, const char* __restrict__ W1h,
               const char* __restrict__ W1l, const char* __restrict__ W2h,
               const char* __restrict__ W2l, const float* __restrict__ g,
               const float* __restrict__ b, float* __restrict__ out, int M) {
    extern __shared__ char smem[];
    char* a_hi = smem;
    char* a_lo = a_hi + 128 * SMSB;
    char* w_hi = a_lo + 128 * SMSB;
    char* w_lo = w_hi + 128 * SMSB;
    char* t_hi = w_lo + 128 * SMSB;
    char* t_lo = t_hi + 128 * SMSB;

    const int tid = threadIdx.x, wid = tid >> 5, lane = tid & 31;
    const int wm = wid >> 2, wn = wid & 3;
    const int q = lane >> 2, t2 = (lane & 3) * 2;
    const int m0 = blockIdx.x * 128;

    float acc2[4][4][4];
#pragma unroll
    for (int mt = 0; mt < 4; mt++)
#pragma unroll
        for (int nt = 0; nt < 4; nt++)
#pragma unroll
            for (int j = 0; j < 4; j++) acc2[mt][nt][j] = 0.0f;

    load_A<1>(X, g, b, M, m0, a_hi, a_lo, tid);

#pragma unroll
    for (int h = 0; h < 2; h++) {
        __syncthreads();  // prior W/T consumers done
        // W1 half h: contiguous rows [128h,128h+128) of [n][k] image (272B rows)
        {
            const char* sH = W1h + (size_t)h * 128 * SMSB;
            const char* sL = W1l + (size_t)h * 128 * SMSB;
#pragma unroll 4
            for (int i = tid * 16; i < 128 * SMSB; i += 256 * 16) {
                *(uint4*)(w_hi + i) = *(const uint4*)(sH + i);
                *(uint4*)(w_lo + i) = *(const uint4*)(sL + i);
            }
        }
        __syncthreads();
        float acc1[4][4][4];
#pragma unroll
        for (int mt = 0; mt < 4; mt++)
#pragma unroll
            for (int nt = 0; nt < 4; nt++)
#pragma unroll
                for (int j = 0; j < 4; j++) acc1[mt][nt][j] = 0.0f;
        compute_tile(acc1, a_hi, a_lo, w_hi, w_lo, wm, wn, q, t2);
        __syncthreads();  // all reads of w_* done before overwrite; T writes follow
        // silu + split -> T
#pragma unroll
        for (int mt = 0; mt < 4; mt++)
#pragma unroll
            for (int nt = 0; nt < 4; nt++) {
                int row0 = wm * 64 + mt * 16 + q;
                int col = wn * 32 + nt * 8 + t2;
#pragma unroll
                for (int half = 0; half < 2; half++) {
                    float s0 = acc1[mt][nt][half * 2 + 0];
                    float s1 = acc1[mt][nt][half * 2 + 1];
                    s0 = s0 / (1.0f + expf(-s0));
                    s1 = s1 / (1.0f + expf(-s1));
                    uint32_t H, L;
                    split2(s0, s1, H, L);
                    int off = (row0 + half * 8) * SMSB + col * 2;
                    *(uint32_t*)(t_hi + off) = H;
                    *(uint32_t*)(t_lo + off) = L;
                }
            }
        // W2 chunk h: rows n 0..127, k bytes [256h, 256h+256) of 528B rows
        {
#pragma unroll 4
            for (int i = tid; i < 128 * 16; i += 256) {
                int n = i >> 4, j = i & 15;
                size_t src = (size_t)n * 528 + (size_t)h * 256 + j * 16;
                int dst = n * SMSB + j * 16;
                *(uint4*)(w_hi + dst) = *(const uint4*)(W2h + src);
                *(uint4*)(w_lo + dst) = *(const uint4*)(W2l + src);
            }
        }
        __syncthreads();
        compute_tile(acc2, t_hi, t_lo, w_hi, w_lo, wm, wn, q, t2);
    }

    // epilogue: + residual X
#pragma unroll
    for (int mt = 0; mt < 4; mt++) {
#pragma unroll
        for (int half = 0; half < 2; half++) {
            int row = m0 + wm * 64 + mt * 16 + q + half * 8;
            if (row >= M) continue;
#pragma unroll
            for (int nt = 0; nt < 4; nt++) {
                int col = wn * 32 + nt * 8 + t2;
                float2 rr = *(const float2*)(X + (size_t)row * 128 + col);
                float o0 = acc2[mt][nt][half * 2 + 0] + rr.x;
                float o1 = acc2[mt][nt][half * 2 + 1] + rr.y;
                *(float2*)(out + (size_t)row * 128 + col) = make_float2(o0, o1);
            }
        }
    }
}

// ====== weight prep: all 10 weights in one launch (grid.y selects) ======
__global__ void prep_all(const float* w0, const float* w1, const float* w2,
                         const float* w3, const float* w4, const float* w5,
                         const float* w6, const float* w7, const float* w8,
                         const float* w9, char* __restrict__ ihb, char* __restrict__ ilb) {
    int y = blockIdx.y;
    const float* W;
    int K = 128, N = 128;
    switch (y) {
        case 0: W = w0; break;
        case 1: W = w1; break;
        case 2: W = w2; break;
        case 3: W = w3; break;
        case 4: W = w4; break;
        case 5: W = w5; break;
        case 6: W = w6; N = 256; break;
        case 7: W = w7; N = 256; break;
        case 8: W = w8; K = 256; break;
        default: W = w9; K = 256; break;
    }
    int idx = blockIdx.x * 256 + threadIdx.x;
    if (idx >= K * N) return;
    int k = idx / N, n = idx % N;
    float w = W[idx];
    __nv_bfloat16 hi = __float2bfloat16(w);
    __nv_bfloat16 lo = __float2bfloat16(w - __bfloat162float(hi));
    size_t off = (size_t)y * 81920 + ((size_t)n * (K + 8) + k) * 2;
    *(unsigned short*)(ihb + off) = __bfloat16_as_ushort(hi);
    *(unsigned short*)(ilb + off) = __bfloat16_as_ushort(lo);
}

// ================= per-edge attention (one warp per edge) =================
__global__ void edge_kernel(const float* __restrict__ Q, const float* __restrict__ K,
                            const float* __restrict__ V, float* __restrict__ PE,
                            const int* __restrict__ eidx, float* __restrict__ wV,
                            float* __restrict__ z, int E) {
    int e = blockIdx.x * 8 + (threadIdx.x >> 5);
    if (e >= E) return;
    int lane = threadIdx.x & 31;
    int src = eidx[e];
    int dst = eidx[E + e];
    int i = lane * 4;
    float4 kv = *(const float4*)(K + (size_t)src * 128 + i);
    float4 qv = *(const float4*)(Q + (size_t)dst * 128 + i);
    float4 pe = *(const float4*)(PE + (size_t)e * 128 + i);
    const float sc = 0.25f;
    float s0 = fminf(fmaxf(kv.x * qv.x * sc, -5.0f), 5.0f) * pe.x;
    float s1 = fminf(fmaxf(kv.y * qv.y * sc, -5.0f), 5.0f) * pe.y;
    float s2 = fminf(fmaxf(kv.z * qv.z * sc, -5.0f), 5.0f) * pe.z;
    float s3 = fminf(fmaxf(kv.w * qv.w * sc, -5.0f), 5.0f) * pe.w;
    *(float4*)(PE + (size_t)e * 128 + i) = make_float4(s0, s1, s2, s3);

    float hs = s0 + s1 + s2 + s3;
    hs += __shfl_xor_sync(0xffffffffu, hs, 1);
    hs += __shfl_xor_sync(0xffffffffu, hs, 2);
    float w = expf(fminf(fmaxf(hs, -5.0f), 5.0f));

    float4 vv = *(const float4*)(V + (size_t)src * 128 + i);
    float* base = wV + (size_t)dst * 128 + i;
    atomicAdd(base + 0, vv.x * w);
    atomicAdd(base + 1, vv.y * w);
    atomicAdd(base + 2, vv.z * w);
    atomicAdd(base + 3, vv.w * w);
    if ((lane & 3) == 0) atomicAdd(z + (size_t)dst * 8 + (lane >> 2), w);
}

__global__ void zero2_kernel(float* __restrict__ a, size_t na,
                             float* __restrict__ bz, size_t nb) {
    size_t i = (size_t)blockIdx.x * blockDim.x + threadIdx.x;
    size_t st = (size_t)gridDim.x * blockDim.x;
    for (size_t k = i; k < na; k += st) a[k] = 0.0f;
    for (size_t k = i; k < nb; k += st) bz[k] = 0.0f;
}

// ================= launch =================
extern "C" void kernel_launch(void* const* d_in, const int* in_sizes, int n_in,
                              void* d_out, int out_size) {
    const float* node = (const float*)d_in[0];
    const float* edge = (const float*)d_in[1];
    const int*   eidx = (const int*)d_in[2];
    const float* Wq = (const float*)d_in[3];
    const float* Wk = (const float*)d_in[4];
    const float* Wv = (const float*)d_in[5];
    const float* We = (const float*)d_in[6];
    const float* Wo_n = (const float*)d_in[7];
    const float* bo_n = (const float*)d_in[8];
    const float* Wo_e = (const float*)d_in[9];
    const float* bo_e = (const float*)d_in[10];
    const float* W1n = (const float*)d_in[11];
    const float* W2n = (const float*)d_in[12];
    const float* W1e = (const float*)d_in[13];
    const float* W2e = (const float*)d_in[14];
    const float* g1n = (const float*)d_in[15];
    const float* b1n = (const float*)d_in[16];
    const float* g1e = (const float*)d_in[17];
    const float* b1e = (const float*)d_in[18];
    const float* g2n = (const float*)d_in[19];
    const float* b2n = (const float*)d_in[20];
    const float* g2e = (const float*)d_in[21];
    const float* b2e = (const float*)d_in[22];

    const int N = in_sizes[0] / 128;
    const int E = in_sizes[1] / 128;
    float* out = (float*)d_out;

    float *Q, *Kb, *Vb, *PE, *wV, *z, *h2, *e2;
    char *wih, *wil;
    cudaGetSymbolAddress((void**)&Q, g_Q);
    cudaGetSymbolAddress((void**)&Kb, g_Kb);
    cudaGetSymbolAddress((void**)&Vb, g_Vb);
    cudaGetSymbolAddress((void**)&PE, g_PE);
    cudaGetSymbolAddress((void**)&wV, g_wV);
    cudaGetSymbolAddress((void**)&z, g_z);
    cudaGetSymbolAddress((void**)&h2, g_h2);
    cudaGetSymbolAddress((void**)&e2, g_e2);
    cudaGetSymbolAddress((void**)&wih, g_wimgh);
    cudaGetSymbolAddress((void**)&wil, g_wimgl);

    auto IH = [&](int i) { return wih + (size_t)i * 81920; };
    auto IL = [&](int i) { return wil + (size_t)i * 81920; };

    const int SMG = 4 * 128 * SMSB;  // 139264
    const int SMF = 6 * 128 * SMSB;  // 208896
    cudaFuncSetAttribute((const void*)mma_gemm<0, 1>, cudaFuncAttributeMaxDynamicSharedMemorySize, SMG);
    cudaFuncSetAttribute((const void*)mma_gemm<1, 0>, cudaFuncAttributeMaxDynamicSharedMemorySize, SMG);
    cudaFuncSetAttribute((const void*)mma_gemm<1, 2>, cudaFuncAttributeMaxDynamicSharedMemorySize, SMG);
    cudaFuncSetAttribute((const void*)ffn_fused, cudaFuncAttributeMaxDynamicSharedMemorySize, SMF);

    const int TtN = (N + 127) / 128;
    const int TtE = (E + 127) / 128;

    // 0) all weight images in one launch
    prep_all<<<dim3(128, 10), 256>>>(Wq, Wk, Wv, We, Wo_n, Wo_e, W1n, W1e, W2n, W2e, wih, wil);

    // 1) fused LN1 + QKV projections (grid.y = slot 0/1/2)
    mma_gemm<0, 1><<<dim3(TtN, 3), 256, SMG>>>(node, g1n, b1n, IH(0), IL(0),
                                               Q, Kb, Vb, nullptr, nullptr, N);
    // 2) fused LN1e + PE projection
    mma_gemm<0, 1><<<dim3(TtE, 1), 256, SMG>>>(edge, g1e, b1e, IH(3), IL(3),
                                               PE, PE, PE, nullptr, nullptr, E);

    // 3) attention aggregation
    zero2_kernel<<<2048, 256>>>(wV, (size_t)N * 128, z, (size_t)N * 8);
    edge_kernel<<<(E + 7) / 8, 256>>>(Q, Kb, Vb, PE, eidx, wV, z, E);

    // 4) output projections (+ bias + residual); node side fuses the z-divide
    mma_gemm<1, 2><<<dim3(TtN, 1), 256, SMG>>>(wV, z, nullptr, IH(4), IL(4),
                                               h2, h2, h2, bo_n, node, N);
    mma_gemm<1, 0><<<dim3(TtE, 1), 256, SMG>>>(PE, nullptr, nullptr, IH(5), IL(5),
                                               e2, e2, e2, bo_e, edge, E);

    // 5) fused LN2 + FFN + residual
    ffn_fused<<<TtN, 256, SMF>>>(h2, IH(6), IL(6), IH(8), IL(8), g2n, b2n, out, N);
    ffn_fused<<<TtE, 256, SMF>>>(e2, IH(7), IL(7), IH(9), IL(9), g2e, b2e,
                                 out + (size_t)N * 128, E);
}

// round 5
// speedup vs baseline: 3.0981x; 1.3756x over previous
#include <cuda_runtime.h>
#include <cuda_fp16.h>
#include <math.h>
#include <stdint.h>

// ================= scratch (device globals) =================
#define NMAX 50000
#define EMAX 400000

__device__ float g_Q  [(size_t)NMAX * 128];
__device__ float g_Kb [(size_t)NMAX * 128];
__device__ float g_Vb [(size_t)NMAX * 128];
__device__ float g_PE [(size_t)EMAX * 128];
__device__ float g_wV [(size_t)NMAX * 128];
__device__ float g_z  [(size_t)NMAX * 8];
__device__ float g_h2 [(size_t)NMAX * 128];
__device__ float g_e2 [(size_t)EMAX * 128];
// weight images: [n][k] fp16, k padded by 8; 10 slots x 80KB, hi and lo
__device__ char g_wimgh[10][81920];
__device__ char g_wimgl[10][81920];

#define SMSB 272  // smem k-stride in bytes (136 fp16)
#define TILEB (128 * SMSB)

// ================= PTX helpers =================
__device__ __forceinline__ uint32_t smem_u32(const void* p) {
    uint32_t a;
    asm("{ .reg .u64 t; cvta.to.shared.u64 t, %1; cvt.u32.u64 %0, t; }" : "=r"(a) : "l"(p));
    return a;
}
__device__ __forceinline__ void cpa16(uint32_t d, const void* s) {
    asm volatile("cp.async.cg.shared.global [%0], [%1], 16;" :: "r"(d), "l"(s));
}
#define CPA_COMMIT() asm volatile("cp.async.commit_group;" ::: "memory")
#define CPA_WAIT(n)  asm volatile("cp.async.wait_group %0;" :: "n"(n) : "memory")

__device__ __forceinline__ void mma_f16(float* c, const uint32_t* a, const uint32_t* b) {
    asm volatile(
        "mma.sync.aligned.m16n8k16.row.col.f32.f16.f16.f32 "
        "{%0,%1,%2,%3}, {%4,%5,%6,%7}, {%8,%9}, {%0,%1,%2,%3};"
        : "+f"(c[0]), "+f"(c[1]), "+f"(c[2]), "+f"(c[3])
        : "r"(a[0]), "r"(a[1]), "r"(a[2]), "r"(a[3]), "r"(b[0]), "r"(b[1]));
}

// 128x128x128 fp16 2-term tile compute; 8 warps in 2x4; acc accumulates.
__device__ __forceinline__ void compute_tile(float (&acc)[4][4][4],
                                             const char* a_sm,
                                             const char* b_hi, const char* b_lo,
                                             int wm, int wn, int q, int t2) {
#pragma unroll
    for (int ks = 0; ks < 8; ks++) {
        uint32_t av[4][4], bh[4][2], bl[4][2];
#pragma unroll
        for (int mt = 0; mt < 4; mt++) {
            int off = (wm * 64 + mt * 16 + q) * SMSB + (ks * 16 + t2) * 2;
            av[mt][0] = *(const uint32_t*)(a_sm + off);
            av[mt][1] = *(const uint32_t*)(a_sm + off + 8 * SMSB);
            av[mt][2] = *(const uint32_t*)(a_sm + off + 16);
            av[mt][3] = *(const uint32_t*)(a_sm + off + 8 * SMSB + 16);
        }
#pragma unroll
        for (int nt = 0; nt < 4; nt++) {
            int off = (wn * 32 + nt * 8 + q) * SMSB + (ks * 16 + t2) * 2;
            bh[nt][0] = *(const uint32_t*)(b_hi + off);
            bh[nt][1] = *(const uint32_t*)(b_hi + off + 16);
            bl[nt][0] = *(const uint32_t*)(b_lo + off);
            bl[nt][1] = *(const uint32_t*)(b_lo + off + 16);
        }
#pragma unroll
        for (int mt = 0; mt < 4; mt++)
#pragma unroll
            for (int nt = 0; nt < 4; nt++) {
                mma_f16(acc[mt][nt], av[mt], bh[nt]);
                mma_f16(acc[mt][nt], av[mt], bl[nt]);
            }
    }
}

// A-load (rows of 128 fp32 -> fp16). ALOAD: 0 plain, 1 LN(P1=g,P2=b), 2 div-by-z(P1=z)
template <int ALOAD>
__device__ __forceinline__ void load_A(const float* __restrict__ A,
                                       const float* __restrict__ P1,
                                       const float* __restrict__ P2,
                                       int M, int m0, char* a_sm, int tid) {
    const int lane = tid & 31;
    float4 gg, bb;
    if (ALOAD == 1) {
        gg = *(const float4*)(P1 + lane * 4);
        bb = *(const float4*)(P2 + lane * 4);
    }
#pragma unroll 4
    for (int i = tid; i < 4096; i += 256) {
        int row = i >> 5;
        float4 v = make_float4(0.f, 0.f, 0.f, 0.f);
        bool valid = (m0 + row < M);
        if (valid) v = *(const float4*)(A + (size_t)(m0 + row) * 128 + lane * 4);
        if (ALOAD == 1) {
            float s = v.x + v.y + v.z + v.w;
#pragma unroll
            for (int o = 16; o; o >>= 1) s += __shfl_xor_sync(0xffffffffu, s, o);
            float mu = s * 0.0078125f;
            float d0 = v.x - mu, d1 = v.y - mu, d2 = v.z - mu, d3 = v.w - mu;
            float qq = d0 * d0 + d1 * d1 + d2 * d2 + d3 * d3;
#pragma unroll
            for (int o = 16; o; o >>= 1) qq += __shfl_xor_sync(0xffffffffu, qq, o);
            float inv = rsqrtf(qq * 0.0078125f + 1e-5f);
            v.x = d0 * inv * gg.x + bb.x;
            v.y = d1 * inv * gg.y + bb.y;
            v.z = d2 * inv * gg.z + bb.z;
            v.w = d3 * inv * gg.w + bb.w;
        } else if (ALOAD == 2) {
            float zz = valid ? P1[(size_t)(m0 + row) * 8 + (lane >> 2)] : 1.0f;
            float inv = 1.0f / (zz + 1e-6f);
            v.x *= inv; v.y *= inv; v.z *= inv; v.w *= inv;
        }
        __half2 p0 = __floats2half2_rn(v.x, v.y);
        __half2 p1 = __floats2half2_rn(v.z, v.w);
        uint2 P;
        P.x = *(const uint32_t*)&p0;
        P.y = *(const uint32_t*)&p1;
        *(uint2*)(a_sm + row * SMSB + lane * 8) = P;
    }
}

// ================= unified HMMA GEMM (K=128): C = op(A) @ Wslot =================
// EPI: 0 none, 1 +bias+residual. grid.y selects B slot and C among C0/C1/C2.
template <int EPI, int ALOAD>
__global__ __launch_bounds__(256, 2)
void mma_gemm(const float* __restrict__ A, const float* __restrict__ P1,
              const float* __restrict__ P2, const char* __restrict__ BhBase,
              const char* __restrict__ BlBase, float* __restrict__ C0,
              float* __restrict__ C1, float* __restrict__ C2,
              const float* __restrict__ bias, const float* __restrict__ Rr, int M) {
    extern __shared__ char smem[];
    char* a_sm = smem;
    char* b_hi = a_sm + TILEB;
    char* b_lo = b_hi + TILEB;
    const uint32_t sb = smem_u32(smem);
    const uint32_t sb_bh = sb + TILEB, sb_bl = sb_bh + TILEB;

    const int tid = threadIdx.x, wid = tid >> 5, lane = tid & 31;
    const int wm = wid >> 2, wn = wid & 3;
    const int q = lane >> 2, t2 = (lane & 3) * 2;
    const int m0 = blockIdx.x * 128;
    const char* Bh = BhBase + (size_t)blockIdx.y * 81920;
    const char* Bl = BlBase + (size_t)blockIdx.y * 81920;
    float* C = (blockIdx.y == 0) ? C0 : (blockIdx.y == 1) ? C1 : C2;

    // async B image copy overlaps A load/convert
    for (int i = tid * 16; i < TILEB; i += 256 * 16) {
        cpa16(sb_bh + i, Bh + i);
        cpa16(sb_bl + i, Bl + i);
    }
    CPA_COMMIT();

    float acc[4][4][4];
#pragma unroll
    for (int mt = 0; mt < 4; mt++)
#pragma unroll
        for (int nt = 0; nt < 4; nt++)
#pragma unroll
            for (int j = 0; j < 4; j++) acc[mt][nt][j] = 0.0f;

    load_A<ALOAD>(A, P1, P2, M, m0, a_sm, tid);
    CPA_WAIT(0);
    __syncthreads();
    compute_tile(acc, a_sm, b_hi, b_lo, wm, wn, q, t2);

#pragma unroll
    for (int mt = 0; mt < 4; mt++) {
#pragma unroll
        for (int half = 0; half < 2; half++) {
            int row = m0 + wm * 64 + mt * 16 + q + half * 8;
            if (row >= M) continue;
#pragma unroll
            for (int nt = 0; nt < 4; nt++) {
                int col = wn * 32 + nt * 8 + t2;
                float o0 = acc[mt][nt][half * 2 + 0];
                float o1 = acc[mt][nt][half * 2 + 1];
                if (EPI == 1) {
                    float2 bbv = *(const float2*)(bias + col);
                    float2 rr = *(const float2*)(Rr + (size_t)row * 128 + col);
                    o0 += bbv.x + rr.x;
                    o1 += bbv.y + rr.y;
                }
                *(float2*)(C + (size_t)row * 128 + col) = make_float2(o0, o1);
            }
        }
    }
}

// ============ fused FFN: out = x + silu(LN(x)@W1) @ W2, per 128-row tile ============
// W prefetch pipeline: groups G0=W1h0, G1=W2c0, G2=W1h1, G3=W2c1 (ping-pong w0/w1).
__global__ __launch_bounds__(256, 1)
void ffn_fused(const float* __restrict__ X, const char* __restrict__ W1h,
               const char* __restrict__ W1l, const char* __restrict__ W2h,
               const char* __restrict__ W2l, const float* __restrict__ g,
               const float* __restrict__ b, float* __restrict__ out, int M) {
    extern __shared__ char smem[];
    char* a_sm = smem;
    char* w0h = a_sm + TILEB;
    char* w0l = w0h + TILEB;
    char* w1h = w0l + TILEB;
    char* w1l = w1h + TILEB;
    char* t_sm = w1l + TILEB;
    const uint32_t sb = smem_u32(smem);
    const uint32_t s_w0h = sb + TILEB, s_w0l = s_w0h + TILEB;
    const uint32_t s_w1h = s_w0l + TILEB, s_w1l = s_w1h + TILEB;

    const int tid = threadIdx.x, wid = tid >> 5, lane = tid & 31;
    const int wm = wid >> 2, wn = wid & 3;
    const int q = lane >> 2, t2 = (lane & 3) * 2;
    const int m0 = blockIdx.x * 128;

    // G0: W1 half0 -> w0 (contiguous 128 rows x 272B)
    for (int i = tid * 16; i < TILEB; i += 4096) {
        cpa16(s_w0h + i, W1h + i);
        cpa16(s_w0l + i, W1l + i);
    }
    CPA_COMMIT();
    // G1: W2 chunk0 -> w1 (strided: rows of 528B, first 256B slice)
    for (int i = tid; i < 128 * 16; i += 256) {
        int n = i >> 4, j = i & 15;
        size_t src = (size_t)n * 528 + j * 16;
        cpa16(s_w1h + n * SMSB + j * 16, W2h + src);
        cpa16(s_w1l + n * SMSB + j * 16, W2l + src);
    }
    CPA_COMMIT();

    load_A<1>(X, g, b, M, m0, a_sm, tid);

    float acc2[4][4][4];
#pragma unroll
    for (int mt = 0; mt < 4; mt++)
#pragma unroll
        for (int nt = 0; nt < 4; nt++)
#pragma unroll
            for (int j = 0; j < 4; j++) acc2[mt][nt][j] = 0.0f;

    float acc1[4][4][4];
#pragma unroll
    for (int h = 0; h < 2; h++) {
        // wait W1 half (G0 or G2): allow 1 outstanding (the W2 group behind it)
        CPA_WAIT(1);
        __syncthreads();
#pragma unroll
        for (int mt = 0; mt < 4; mt++)
#pragma unroll
            for (int nt = 0; nt < 4; nt++)
#pragma unroll
                for (int j = 0; j < 4; j++) acc1[mt][nt][j] = 0.0f;
        compute_tile(acc1, a_sm, w0h, w0l, wm, wn, q, t2);
        __syncthreads();  // w0 reads done before overwrite; t reads (prev iter) done
        if (h == 0) {
            // G2: W1 half1 -> w0
            for (int i = tid * 16; i < TILEB; i += 4096) {
                cpa16(s_w0h + i, W1h + TILEB + i);
                cpa16(s_w0l + i, W1l + TILEB + i);
            }
            CPA_COMMIT();
        }
        // silu + fp16 -> t
#pragma unroll
        for (int mt = 0; mt < 4; mt++)
#pragma unroll
            for (int nt = 0; nt < 4; nt++) {
                int row0 = wm * 64 + mt * 16 + q;
                int col = wn * 32 + nt * 8 + t2;
#pragma unroll
                for (int half = 0; half < 2; half++) {
                    float s0 = acc1[mt][nt][half * 2 + 0];
                    float s1 = acc1[mt][nt][half * 2 + 1];
                    s0 = s0 / (1.0f + expf(-s0));
                    s1 = s1 / (1.0f + expf(-s1));
                    __half2 p = __floats2half2_rn(s0, s1);
                    *(uint32_t*)(t_sm + (row0 + half * 8) * SMSB + col * 2) =
                        *(const uint32_t*)&p;
                }
            }
        // wait W2 chunk (G1 or G3)
        if (h == 0) CPA_WAIT(1); else CPA_WAIT(0);
        __syncthreads();
        compute_tile(acc2, t_sm, w1h, w1l, wm, wn, q, t2);
        __syncthreads();  // w1/t reads done
        if (h == 0) {
            // G3: W2 chunk1 -> w1
            for (int i = tid; i < 128 * 16; i += 256) {
                int n = i >> 4, j = i & 15;
                size_t src = (size_t)n * 528 + 256 + j * 16;
                cpa16(s_w1h + n * SMSB + j * 16, W2h + src);
                cpa16(s_w1l + n * SMSB + j * 16, W2l + src);
            }
            CPA_COMMIT();
        }
    }

    // epilogue: + residual X
#pragma unroll
    for (int mt = 0; mt < 4; mt++) {
#pragma unroll
        for (int half = 0; half < 2; half++) {
            int row = m0 + wm * 64 + mt * 16 + q + half * 8;
            if (row >= M) continue;
#pragma unroll
            for (int nt = 0; nt < 4; nt++) {
                int col = wn * 32 + nt * 8 + t2;
                float2 rr = *(const float2*)(X + (size_t)row * 128 + col);
                float o0 = acc2[mt][nt][half * 2 + 0] + rr.x;
                float o1 = acc2[mt][nt][half * 2 + 1] + rr.y;
                *(float2*)(out + (size_t)row * 128 + col) = make_float2(o0, o1);
            }
        }
    }
}

// ====== weight prep: all 10 weights, fp16 hi/lo split, one launch ======
__global__ void prep_all(const float* w0, const float* w1, const float* w2,
                         const float* w3, const float* w4, const float* w5,
                         const float* w6, const float* w7, const float* w8,
                         const float* w9, char* __restrict__ ihb, char* __restrict__ ilb) {
    int y = blockIdx.y;
    const float* W;
    int K = 128, N = 128;
    switch (y) {
        case 0: W = w0; break;
        case 1: W = w1; break;
        case 2: W = w2; break;
        case 3: W = w3; break;
        case 4: W = w4; break;
        case 5: W = w5; break;
        case 6: W = w6; N = 256; break;
        case 7: W = w7; N = 256; break;
        case 8: W = w8; K = 256; break;
        default: W = w9; K = 256; break;
    }
    int idx = blockIdx.x * 256 + threadIdx.x;
    if (idx >= K * N) return;
    int k = idx / N, n = idx % N;
    float w = W[idx];
    __half hi = __float2half_rn(w);
    __half lo = __float2half_rn(w - __half2float(hi));
    size_t off = (size_t)y * 81920 + ((size_t)n * (K + 8) + k) * 2;
    *(unsigned short*)(ihb + off) = __half_as_ushort(hi);
    *(unsigned short*)(ilb + off) = __half_as_ushort(lo);
}

// ================= per-edge attention (one warp per edge) =================
__global__ void edge_kernel(const float* __restrict__ Q, const float* __restrict__ K,
                            const float* __restrict__ V, float* __restrict__ PE,
                            const int* __restrict__ eidx, float* __restrict__ wV,
                            float* __restrict__ z, int E) {
    int e = blockIdx.x * 8 + (threadIdx.x >> 5);
    if (e >= E) return;
    int lane = threadIdx.x & 31;
    int src = eidx[e];
    int dst = eidx[E + e];
    int i = lane * 4;
    float4 kv = *(const float4*)(K + (size_t)src * 128 + i);
    float4 qv = *(const float4*)(Q + (size_t)dst * 128 + i);
    float4 pe = *(const float4*)(PE + (size_t)e * 128 + i);
    const float sc = 0.25f;
    float s0 = fminf(fmaxf(kv.x * qv.x * sc, -5.0f), 5.0f) * pe.x;
    float s1 = fminf(fmaxf(kv.y * qv.y * sc, -5.0f), 5.0f) * pe.y;
    float s2 = fminf(fmaxf(kv.z * qv.z * sc, -5.0f), 5.0f) * pe.z;
    float s3 = fminf(fmaxf(kv.w * qv.w * sc, -5.0f), 5.0f) * pe.w;
    *(float4*)(PE + (size_t)e * 128 + i) = make_float4(s0, s1, s2, s3);

    float hs = s0 + s1 + s2 + s3;
    hs += __shfl_xor_sync(0xffffffffu, hs, 1);
    hs += __shfl_xor_sync(0xffffffffu, hs, 2);
    float w = expf(fminf(fmaxf(hs, -5.0f), 5.0f));

    float4 vv = *(const float4*)(V + (size_t)src * 128 + i);
    float* base = wV + (size_t)dst * 128 + i;
    atomicAdd(base + 0, vv.x * w);
    atomicAdd(base + 1, vv.y * w);
    atomicAdd(base + 2, vv.z * w);
    atomicAdd(base + 3, vv.w * w);
    if ((lane & 3) == 0) atomicAdd(z + (size_t)dst * 8 + (lane >> 2), w);
}

__global__ void zero2_kernel(float* __restrict__ a, size_t na,
                             float* __restrict__ bz, size_t nb) {
    size_t i = (size_t)blockIdx.x * blockDim.x + threadIdx.x;
    size_t st = (size_t)gridDim.x * blockDim.x;
    for (size_t k = i; k < na; k += st) a[k] = 0.0f;
    for (size_t k = i; k < nb; k += st) bz[k] = 0.0f;
}

// ================= launch =================
extern "C" void kernel_launch(void* const* d_in, const int* in_sizes, int n_in,
                              void* d_out, int out_size) {
    const float* node = (const float*)d_in[0];
    const float* edge = (const float*)d_in[1];
    const int*   eidx = (const int*)d_in[2];
    const float* Wq = (const float*)d_in[3];
    const float* Wk = (const float*)d_in[4];
    const float* Wv = (const float*)d_in[5];
    const float* We = (const float*)d_in[6];
    const float* Wo_n = (const float*)d_in[7];
    const float* bo_n = (const float*)d_in[8];
    const float* Wo_e = (const float*)d_in[9];
    const float* bo_e = (const float*)d_in[10];
    const float* W1n = (const float*)d_in[11];
    const float* W2n = (const float*)d_in[12];
    const float* W1e = (const float*)d_in[13];
    const float* W2e = (const float*)d_in[14];
    const float* g1n = (const float*)d_in[15];
    const float* b1n = (const float*)d_in[16];
    const float* g1e = (const float*)d_in[17];
    const float* b1e = (const float*)d_in[18];
    const float* g2n = (const float*)d_in[19];
    const float* b2n = (const float*)d_in[20];
    const float* g2e = (const float*)d_in[21];
    const float* b2e = (const float*)d_in[22];

    const int N = in_sizes[0] / 128;
    const int E = in_sizes[1] / 128;
    float* out = (float*)d_out;

    float *Q, *Kb, *Vb, *PE, *wV, *z, *h2, *e2;
    char *wih, *wil;
    cudaGetSymbolAddress((void**)&Q, g_Q);
    cudaGetSymbolAddress((void**)&Kb, g_Kb);
    cudaGetSymbolAddress((void**)&Vb, g_Vb);
    cudaGetSymbolAddress((void**)&PE, g_PE);
    cudaGetSymbolAddress((void**)&wV, g_wV);
    cudaGetSymbolAddress((void**)&z, g_z);
    cudaGetSymbolAddress((void**)&h2, g_h2);
    cudaGetSymbolAddress((void**)&e2, g_e2);
    cudaGetSymbolAddress((void**)&wih, g_wimgh);
    cudaGetSymbolAddress((void**)&wil, g_wimgl);

    auto IH = [&](int i) { return wih + (size_t)i * 81920; };
    auto IL = [&](int i) { return wil + (size_t)i * 81920; };

    const int SMG = 3 * TILEB;  // 104448
    const int SMF = 6 * TILEB;  // 208896
    cudaFuncSetAttribute((const void*)mma_gemm<0, 1>, cudaFuncAttributeMaxDynamicSharedMemorySize, SMG);
    cudaFuncSetAttribute((const void*)mma_gemm<1, 0>, cudaFuncAttributeMaxDynamicSharedMemorySize, SMG);
    cudaFuncSetAttribute((const void*)mma_gemm<1, 2>, cudaFuncAttributeMaxDynamicSharedMemorySize, SMG);
    cudaFuncSetAttribute((const void*)ffn_fused, cudaFuncAttributeMaxDynamicSharedMemorySize, SMF);

    const int TtN = (N + 127) / 128;
    const int TtE = (E + 127) / 128;

    // 0) all weight images in one launch
    prep_all<<<dim3(128, 10), 256>>>(Wq, Wk, Wv, We, Wo_n, Wo_e, W1n, W1e, W2n, W2e, wih, wil);

    // 1) fused LN1 + QKV projections (grid.y = slot 0/1/2)
    mma_gemm<0, 1><<<dim3(TtN, 3), 256, SMG>>>(node, g1n, b1n, IH(0), IL(0),
                                               Q, Kb, Vb, nullptr, nullptr, N);
    // 2) fused LN1e + PE projection
    mma_gemm<0, 1><<<dim3(TtE, 1), 256, SMG>>>(edge, g1e, b1e, IH(3), IL(3),
                                               PE, PE, PE, nullptr, nullptr, E);

    // 3) attention aggregation
    zero2_kernel<<<2048, 256>>>(wV, (size_t)N * 128, z, (size_t)N * 8);
    edge_kernel<<<(E + 7) / 8, 256>>>(Q, Kb, Vb, PE, eidx, wV, z, E);

    // 4) output projections (+ bias + residual); node side fuses the z-divide
    mma_gemm<1, 2><<<dim3(TtN, 1), 256, SMG>>>(wV, z, nullptr, IH(4), IL(4),
                                               h2, h2, h2, bo_n, node, N);
    mma_gemm<1, 0><<<dim3(TtE, 1), 256, SMG>>>(PE, nullptr, nullptr, IH(5), IL(5),
                                               e2, e2, e2, bo_e, edge, E);

    // 5) fused LN2 + FFN + residual
    ffn_fused<<<TtN, 256, SMF>>>(h2, IH(6), IL(6), IH(8), IL(8), g2n, b2n, out, N);
    ffn_fused<<<TtE, 256, SMF>>>(e2, IH(7), IL(7), IH(9), IL(9), g2e, b2e,
                                 out + (size_t)N * 128, E);
}

// round 6
// speedup vs baseline: 3.6267x; 1.1706x over previous
#include <cuda_runtime.h>
#include <cuda_fp16.h>
#include <math.h>
#include <stdint.h>

// ================= scratch (device globals) =================
#define NMAX 50000
#define EMAX 400000

__device__ float g_Q  [(size_t)NMAX * 128];
__device__ float g_Kb [(size_t)NMAX * 128];
__device__ float g_Vb [(size_t)NMAX * 128];
__device__ float g_PE [(size_t)EMAX * 128];
__device__ float g_wV [(size_t)NMAX * 128];
__device__ float g_z  [(size_t)NMAX * 8];
__device__ float g_h2 [(size_t)NMAX * 128];
__device__ float g_e2 [(size_t)EMAX * 128];
// weight images: [n][k] fp16, k padded by 8; 10 slots x 80KB
__device__ char g_wimg[10][81920];

#define SMSB 272  // smem k-stride in bytes (136 fp16)
#define TILEB (128 * SMSB)

// ================= PTX helpers =================
__device__ __forceinline__ uint32_t smem_u32(const void* p) {
    uint32_t a;
    asm("{ .reg .u64 t; cvta.to.shared.u64 t, %1; cvt.u32.u64 %0, t; }" : "=r"(a) : "l"(p));
    return a;
}
__device__ __forceinline__ void cpa16(uint32_t d, const void* s) {
    asm volatile("cp.async.cg.shared.global [%0], [%1], 16;" :: "r"(d), "l"(s));
}
#define CPA_COMMIT() asm volatile("cp.async.commit_group;" ::: "memory")
#define CPA_WAIT(n)  asm volatile("cp.async.wait_group %0;" :: "n"(n) : "memory")

__device__ __forceinline__ void mma_f16(float* c, const uint32_t* a, const uint32_t* b) {
    asm volatile(
        "mma.sync.aligned.m16n8k16.row.col.f32.f16.f16.f32 "
        "{%0,%1,%2,%3}, {%4,%5,%6,%7}, {%8,%9}, {%0,%1,%2,%3};"
        : "+f"(c[0]), "+f"(c[1]), "+f"(c[2]), "+f"(c[3])
        : "r"(a[0]), "r"(a[1]), "r"(a[2]), "r"(a[3]), "r"(b[0]), "r"(b[1]));
}

// 128x128x128 fp16 tile compute; 8 warps in 2x4; acc accumulates.
__device__ __forceinline__ void compute_tile(float (&acc)[4][4][4],
                                             const char* a_sm, const char* b_sm,
                                             int wm, int wn, int q, int t2) {
#pragma unroll
    for (int ks = 0; ks < 8; ks++) {
        uint32_t av[4][4], bv[4][2];
#pragma unroll
        for (int mt = 0; mt < 4; mt++) {
            int off = (wm * 64 + mt * 16 + q) * SMSB + (ks * 16 + t2) * 2;
            av[mt][0] = *(const uint32_t*)(a_sm + off);
            av[mt][1] = *(const uint32_t*)(a_sm + off + 8 * SMSB);
            av[mt][2] = *(const uint32_t*)(a_sm + off + 16);
            av[mt][3] = *(const uint32_t*)(a_sm + off + 8 * SMSB + 16);
        }
#pragma unroll
        for (int nt = 0; nt < 4; nt++) {
            int off = (wn * 32 + nt * 8 + q) * SMSB + (ks * 16 + t2) * 2;
            bv[nt][0] = *(const uint32_t*)(b_sm + off);
            bv[nt][1] = *(const uint32_t*)(b_sm + off + 16);
        }
#pragma unroll
        for (int mt = 0; mt < 4; mt++)
#pragma unroll
            for (int nt = 0; nt < 4; nt++) mma_f16(acc[mt][nt], av[mt], bv[nt]);
    }
}

// A-load (rows of 128 fp32 -> fp16). ALOAD: 0 plain, 1 LN(P1=g,P2=b), 2 div-by-z(P1=z)
template <int ALOAD>
__device__ __forceinline__ void load_A(const float* __restrict__ A,
                                       const float* __restrict__ P1,
                                       const float* __restrict__ P2,
                                       int M, int m0, char* a_sm, int tid) {
    const int lane = tid & 31;
    float4 gg, bb;
    if (ALOAD == 1) {
        gg = *(const float4*)(P1 + lane * 4);
        bb = *(const float4*)(P2 + lane * 4);
    }
#pragma unroll 4
    for (int i = tid; i < 4096; i += 256) {
        int row = i >> 5;
        float4 v = make_float4(0.f, 0.f, 0.f, 0.f);
        bool valid = (m0 + row < M);
        if (valid) v = *(const float4*)(A + (size_t)(m0 + row) * 128 + lane * 4);
        if (ALOAD == 1) {
            float s = v.x + v.y + v.z + v.w;
#pragma unroll
            for (int o = 16; o; o >>= 1) s += __shfl_xor_sync(0xffffffffu, s, o);
            float mu = s * 0.0078125f;
            float d0 = v.x - mu, d1 = v.y - mu, d2 = v.z - mu, d3 = v.w - mu;
            float qq = d0 * d0 + d1 * d1 + d2 * d2 + d3 * d3;
#pragma unroll
            for (int o = 16; o; o >>= 1) qq += __shfl_xor_sync(0xffffffffu, qq, o);
            float inv = rsqrtf(qq * 0.0078125f + 1e-5f);
            v.x = d0 * inv * gg.x + bb.x;
            v.y = d1 * inv * gg.y + bb.y;
            v.z = d2 * inv * gg.z + bb.z;
            v.w = d3 * inv * gg.w + bb.w;
        } else if (ALOAD == 2) {
            float zz = valid ? P1[(size_t)(m0 + row) * 8 + (lane >> 2)] : 1.0f;
            float inv = 1.0f / (zz + 1e-6f);
            v.x *= inv; v.y *= inv; v.z *= inv; v.w *= inv;
        }
        __half2 p0 = __floats2half2_rn(v.x, v.y);
        __half2 p1 = __floats2half2_rn(v.z, v.w);
        uint2 P;
        P.x = *(const uint32_t*)&p0;
        P.y = *(const uint32_t*)&p1;
        *(uint2*)(a_sm + row * SMSB + lane * 8) = P;
    }
}

// ================= unified HMMA GEMM (K=128): C = op(A) @ Wslot =================
// EPI: 0 none, 1 +bias+residual. grid.y selects B slot and C among C0/C1/C2.
template <int EPI, int ALOAD>
__global__ __launch_bounds__(256, 2)
void mma_gemm(const float* __restrict__ A, const float* __restrict__ P1,
              const float* __restrict__ P2, const char* __restrict__ BBase,
              float* __restrict__ C0, float* __restrict__ C1, float* __restrict__ C2,
              const float* __restrict__ bias, const float* __restrict__ Rr, int M) {
    extern __shared__ char smem[];
    char* a_sm = smem;
    char* b_sm = a_sm + TILEB;
    const uint32_t sb_b = smem_u32(smem) + TILEB;

    const int tid = threadIdx.x, wid = tid >> 5, lane = tid & 31;
    const int wm = wid >> 2, wn = wid & 3;
    const int q = lane >> 2, t2 = (lane & 3) * 2;
    const int m0 = blockIdx.x * 128;
    const char* Bg = BBase + (size_t)blockIdx.y * 81920;
    float* C = (blockIdx.y == 0) ? C0 : (blockIdx.y == 1) ? C1 : C2;

    // async B image copy overlaps A load/convert
    for (int i = tid * 16; i < TILEB; i += 4096) cpa16(sb_b + i, Bg + i);
    CPA_COMMIT();

    float acc[4][4][4];
#pragma unroll
    for (int mt = 0; mt < 4; mt++)
#pragma unroll
        for (int nt = 0; nt < 4; nt++)
#pragma unroll
            for (int j = 0; j < 4; j++) acc[mt][nt][j] = 0.0f;

    load_A<ALOAD>(A, P1, P2, M, m0, a_sm, tid);
    CPA_WAIT(0);
    __syncthreads();
    compute_tile(acc, a_sm, b_sm, wm, wn, q, t2);

#pragma unroll
    for (int mt = 0; mt < 4; mt++) {
#pragma unroll
        for (int half = 0; half < 2; half++) {
            int row = m0 + wm * 64 + mt * 16 + q + half * 8;
            if (row >= M) continue;
#pragma unroll
            for (int nt = 0; nt < 4; nt++) {
                int col = wn * 32 + nt * 8 + t2;
                float o0 = acc[mt][nt][half * 2 + 0];
                float o1 = acc[mt][nt][half * 2 + 1];
                if (EPI == 1) {
                    float2 bbv = *(const float2*)(bias + col);
                    float2 rr = *(const float2*)(Rr + (size_t)row * 128 + col);
                    o0 += bbv.x + rr.x;
                    o1 += bbv.y + rr.y;
                }
                *(float2*)(C + (size_t)row * 128 + col) = make_float2(o0, o1);
            }
        }
    }
}

// ============ fused FFN: out = x + silu(LN(x)@W1) @ W2, per 128-row tile ============
// W prefetch pipeline: groups G0=W1h0, G1=W2c0, G2=W1h1, G3=W2c1 (ping-pong w0/w1).
__global__ __launch_bounds__(256, 1)
void ffn_fused(const float* __restrict__ X, const char* __restrict__ W1,
               const char* __restrict__ W2, const float* __restrict__ g,
               const float* __restrict__ b, float* __restrict__ out, int M) {
    extern __shared__ char smem[];
    char* a_sm = smem;
    char* w0 = a_sm + TILEB;
    char* w1 = w0 + TILEB;
    char* t_sm = w1 + TILEB;
    const uint32_t sb = smem_u32(smem);
    const uint32_t s_w0 = sb + TILEB, s_w1 = s_w0 + TILEB;

    const int tid = threadIdx.x, wid = tid >> 5, lane = tid & 31;
    const int wm = wid >> 2, wn = wid & 3;
    const int q = lane >> 2, t2 = (lane & 3) * 2;
    const int m0 = blockIdx.x * 128;

    // G0: W1 half0 -> w0 (contiguous 128 rows x 272B)
    for (int i = tid * 16; i < TILEB; i += 4096) cpa16(s_w0 + i, W1 + i);
    CPA_COMMIT();
    // G1: W2 chunk0 -> w1 (strided: rows of 528B, first 256B slice)
    for (int i = tid; i < 128 * 16; i += 256) {
        int n = i >> 4, j = i & 15;
        cpa16(s_w1 + n * SMSB + j * 16, W2 + (size_t)n * 528 + j * 16);
    }
    CPA_COMMIT();

    load_A<1>(X, g, b, M, m0, a_sm, tid);

    float acc2[4][4][4];
#pragma unroll
    for (int mt = 0; mt < 4; mt++)
#pragma unroll
        for (int nt = 0; nt < 4; nt++)
#pragma unroll
            for (int j = 0; j < 4; j++) acc2[mt][nt][j] = 0.0f;

    float acc1[4][4][4];
#pragma unroll
    for (int h = 0; h < 2; h++) {
        // wait W1 half (G0 or G2): allow 1 outstanding (the W2 group behind it)
        CPA_WAIT(1);
        __syncthreads();
#pragma unroll
        for (int mt = 0; mt < 4; mt++)
#pragma unroll
            for (int nt = 0; nt < 4; nt++)
#pragma unroll
                for (int j = 0; j < 4; j++) acc1[mt][nt][j] = 0.0f;
        compute_tile(acc1, a_sm, w0, wm, wn, q, t2);
        __syncthreads();  // w0 reads done before overwrite; t reads (prev iter) done
        if (h == 0) {
            // G2: W1 half1 -> w0
            for (int i = tid * 16; i < TILEB; i += 4096) cpa16(s_w0 + i, W1 + TILEB + i);
            CPA_COMMIT();
        }
        // silu + fp16 -> t
#pragma unroll
        for (int mt = 0; mt < 4; mt++)
#pragma unroll
            for (int nt = 0; nt < 4; nt++) {
                int row0 = wm * 64 + mt * 16 + q;
                int col = wn * 32 + nt * 8 + t2;
#pragma unroll
                for (int half = 0; half < 2; half++) {
                    float s0 = acc1[mt][nt][half * 2 + 0];
                    float s1 = acc1[mt][nt][half * 2 + 1];
                    s0 = s0 / (1.0f + expf(-s0));
                    s1 = s1 / (1.0f + expf(-s1));
                    __half2 p = __floats2half2_rn(s0, s1);
                    *(uint32_t*)(t_sm + (row0 + half * 8) * SMSB + col * 2) =
                        *(const uint32_t*)&p;
                }
            }
        // wait W2 chunk (G1 or G3)
        if (h == 0) CPA_WAIT(1); else CPA_WAIT(0);
        __syncthreads();
        compute_tile(acc2, t_sm, w1, wm, wn, q, t2);
        __syncthreads();  // w1/t reads done
        if (h == 0) {
            // G3: W2 chunk1 -> w1
            for (int i = tid; i < 128 * 16; i += 256) {
                int n = i >> 4, j = i & 15;
                cpa16(s_w1 + n * SMSB + j * 16, W2 + (size_t)n * 528 + 256 + j * 16);
            }
            CPA_COMMIT();
        }
    }

    // epilogue: + residual X
#pragma unroll
    for (int mt = 0; mt < 4; mt++) {
#pragma unroll
        for (int half = 0; half < 2; half++) {
            int row = m0 + wm * 64 + mt * 16 + q + half * 8;
            if (row >= M) continue;
#pragma unroll
            for (int nt = 0; nt < 4; nt++) {
                int col = wn * 32 + nt * 8 + t2;
                float2 rr = *(const float2*)(X + (size_t)row * 128 + col);
                float o0 = acc2[mt][nt][half * 2 + 0] + rr.x;
                float o1 = acc2[mt][nt][half * 2 + 1] + rr.y;
                *(float2*)(out + (size_t)row * 128 + col) = make_float2(o0, o1);
            }
        }
    }
}

// ====== weight prep: all 10 weights, fp16, one launch ======
__global__ void prep_all(const float* w0, const float* w1, const float* w2,
                         const float* w3, const float* w4, const float* w5,
                         const float* w6, const float* w7, const float* w8,
                         const float* w9, char* __restrict__ ib) {
    int y = blockIdx.y;
    const float* W;
    int K = 128, N = 128;
    switch (y) {
        case 0: W = w0; break;
        case 1: W = w1; break;
        case 2: W = w2; break;
        case 3: W = w3; break;
        case 4: W = w4; break;
        case 5: W = w5; break;
        case 6: W = w6; N = 256; break;
        case 7: W = w7; N = 256; break;
        case 8: W = w8; K = 256; break;
        default: W = w9; K = 256; break;
    }
    int idx = blockIdx.x * 256 + threadIdx.x;
    if (idx >= K * N) return;
    int k = idx / N, n = idx % N;
    size_t off = (size_t)y * 81920 + ((size_t)n * (K + 8) + k) * 2;
    *(unsigned short*)(ib + off) = __half_as_ushort(__float2half_rn(W[idx]));
}

// ================= per-edge attention (one warp per edge) =================
__global__ void edge_kernel(const float* __restrict__ Q, const float* __restrict__ K,
                            const float* __restrict__ V, float* __restrict__ PE,
                            const int* __restrict__ eidx, float* __restrict__ wV,
                            float* __restrict__ z, int E) {
    int e = blockIdx.x * 8 + (threadIdx.x >> 5);
    if (e >= E) return;
    int lane = threadIdx.x & 31;
    int src = eidx[e];
    int dst = eidx[E + e];
    int i = lane * 4;
    float4 kv = *(const float4*)(K + (size_t)src * 128 + i);
    float4 qv = *(const float4*)(Q + (size_t)dst * 128 + i);
    float4 pe = *(const float4*)(PE + (size_t)e * 128 + i);
    const float sc = 0.25f;
    float s0 = fminf(fmaxf(kv.x * qv.x * sc, -5.0f), 5.0f) * pe.x;
    float s1 = fminf(fmaxf(kv.y * qv.y * sc, -5.0f), 5.0f) * pe.y;
    float s2 = fminf(fmaxf(kv.z * qv.z * sc, -5.0f), 5.0f) * pe.z;
    float s3 = fminf(fmaxf(kv.w * qv.w * sc, -5.0f), 5.0f) * pe.w;
    *(float4*)(PE + (size_t)e * 128 + i) = make_float4(s0, s1, s2, s3);

    float hs = s0 + s1 + s2 + s3;
    hs += __shfl_xor_sync(0xffffffffu, hs, 1);
    hs += __shfl_xor_sync(0xffffffffu, hs, 2);
    float w = expf(fminf(fmaxf(hs, -5.0f), 5.0f));

    float4 vv = *(const float4*)(V + (size_t)src * 128 + i);
    float* base = wV + (size_t)dst * 128 + i;
    atomicAdd(base + 0, vv.x * w);
    atomicAdd(base + 1, vv.y * w);
    atomicAdd(base + 2, vv.z * w);
    atomicAdd(base + 3, vv.w * w);
    if ((lane & 3) == 0) atomicAdd(z + (size_t)dst * 8 + (lane >> 2), w);
}

__global__ void zero2_kernel(float* __restrict__ a, size_t na,
                             float* __restrict__ bz, size_t nb) {
    size_t i = (size_t)blockIdx.x * blockDim.x + threadIdx.x;
    size_t st = (size_t)gridDim.x * blockDim.x;
    for (size_t k = i; k < na; k += st) a[k] = 0.0f;
    for (size_t k = i; k < nb; k += st) bz[k] = 0.0f;
}

// ================= launch =================
extern "C" void kernel_launch(void* const* d_in, const int* in_sizes, int n_in,
                              void* d_out, int out_size) {
    const float* node = (const float*)d_in[0];
    const float* edge = (const float*)d_in[1];
    const int*   eidx = (const int*)d_in[2];
    const float* Wq = (const float*)d_in[3];
    const float* Wk = (const float*)d_in[4];
    const float* Wv = (const float*)d_in[5];
    const float* We = (const float*)d_in[6];
    const float* Wo_n = (const float*)d_in[7];
    const float* bo_n = (const float*)d_in[8];
    const float* Wo_e = (const float*)d_in[9];
    const float* bo_e = (const float*)d_in[10];
    const float* W1n = (const float*)d_in[11];
    const float* W2n = (const float*)d_in[12];
    const float* W1e = (const float*)d_in[13];
    const float* W2e = (const float*)d_in[14];
    const float* g1n = (const float*)d_in[15];
    const float* b1n = (const float*)d_in[16];
    const float* g1e = (const float*)d_in[17];
    const float* b1e = (const float*)d_in[18];
    const float* g2n = (const float*)d_in[19];
    const float* b2n = (const float*)d_in[20];
    const float* g2e = (const float*)d_in[21];
    const float* b2e = (const float*)d_in[22];

    const int N = in_sizes[0] / 128;
    const int E = in_sizes[1] / 128;
    float* out = (float*)d_out;

    float *Q, *Kb, *Vb, *PE, *wV, *z, *h2, *e2;
    char* wim;
    cudaGetSymbolAddress((void**)&Q, g_Q);
    cudaGetSymbolAddress((void**)&Kb, g_Kb);
    cudaGetSymbolAddress((void**)&Vb, g_Vb);
    cudaGetSymbolAddress((void**)&PE, g_PE);
    cudaGetSymbolAddress((void**)&wV, g_wV);
    cudaGetSymbolAddress((void**)&z, g_z);
    cudaGetSymbolAddress((void**)&h2, g_h2);
    cudaGetSymbolAddress((void**)&e2, g_e2);
    cudaGetSymbolAddress((void**)&wim, g_wimg);

    auto IM = [&](int i) { return wim + (size_t)i * 81920; };

    const int SMG = 2 * TILEB;  // 69632
    const int SMF = 4 * TILEB;  // 139264
    cudaFuncSetAttribute((const void*)mma_gemm<0, 1>, cudaFuncAttributeMaxDynamicSharedMemorySize, SMG);
    cudaFuncSetAttribute((const void*)mma_gemm<1, 0>, cudaFuncAttributeMaxDynamicSharedMemorySize, SMG);
    cudaFuncSetAttribute((const void*)mma_gemm<1, 2>, cudaFuncAttributeMaxDynamicSharedMemorySize, SMG);
    cudaFuncSetAttribute((const void*)ffn_fused, cudaFuncAttributeMaxDynamicSharedMemorySize, SMF);

    const int TtN = (N + 127) / 128;
    const int TtE = (E + 127) / 128;

    // 0) all weight images in one launch
    prep_all<<<dim3(128, 10), 256>>>(Wq, Wk, Wv, We, Wo_n, Wo_e, W1n, W1e, W2n, W2e, wim);

    // 1) fused LN1 + QKV projections (grid.y = slot 0/1/2)
    mma_gemm<0, 1><<<dim3(TtN, 3), 256, SMG>>>(node, g1n, b1n, IM(0),
                                               Q, Kb, Vb, nullptr, nullptr, N);
    // 2) fused LN1e + PE projection
    mma_gemm<0, 1><<<dim3(TtE, 1), 256, SMG>>>(edge, g1e, b1e, IM(3),
                                               PE, PE, PE, nullptr, nullptr, E);

    // 3) attention aggregation
    zero2_kernel<<<2048, 256>>>(wV, (size_t)N * 128, z, (size_t)N * 8);
    edge_kernel<<<(E + 7) / 8, 256>>>(Q, Kb, Vb, PE, eidx, wV, z, E);

    // 4) output projections (+ bias + residual); node side fuses the z-divide
    mma_gemm<1, 2><<<dim3(TtN, 1), 256, SMG>>>(wV, z, nullptr, IM(4),
                                               h2, h2, h2, bo_n, node, N);
    mma_gemm<1, 0><<<dim3(TtE, 1), 256, SMG>>>(PE, nullptr, nullptr, IM(5),
                                               e2, e2, e2, bo_e, edge, E);

    // 5) fused LN2 + FFN + residual
    ffn_fused<<<TtN, 256, SMF>>>(h2, IM(6), IM(8), g2n, b2n, out, N);
    ffn_fused<<<TtE, 256, SMF>>>(e2, IM(7), IM(9), g2e, b2e,
                                 out + (size_t)N * 128, E);
}

// round 7
// speedup vs baseline: 3.9495x; 1.0890x over previous
#include <cuda_runtime.h>
#include <cuda_fp16.h>
#include <math.h>
#include <stdint.h>

// ================= scratch (device globals) =================
#define NMAX 50000
#define EMAX 400000

__device__ __half g_Q [(size_t)NMAX * 128];
__device__ __half g_Kb[(size_t)NMAX * 128];
__device__ __half g_Vb[(size_t)NMAX * 128];
__device__ __half g_PE[(size_t)EMAX * 128];   // PE -> overwritten with e_attn
__device__ float g_wV [(size_t)NMAX * 128];
__device__ float g_z  [(size_t)NMAX * 8];
__device__ float g_h2 [(size_t)NMAX * 128];
__device__ float g_e2 [(size_t)EMAX * 128];
// weight images: [n][k] fp16, k padded by 8; 10 slots x 80KB
__device__ char g_wimg[10][81920];

#define SMSB 272  // smem k-stride in bytes (136 fp16)
#define TILEB (128 * SMSB)

// ================= PTX helpers =================
__device__ __forceinline__ uint32_t smem_u32(const void* p) {
    uint32_t a;
    asm("{ .reg .u64 t; cvta.to.shared.u64 t, %1; cvt.u32.u64 %0, t; }" : "=r"(a) : "l"(p));
    return a;
}
__device__ __forceinline__ void cpa16(uint32_t d, const void* s) {
    asm volatile("cp.async.cg.shared.global [%0], [%1], 16;" :: "r"(d), "l"(s));
}
#define CPA_COMMIT() asm volatile("cp.async.commit_group;" ::: "memory")
#define CPA_WAIT(n)  asm volatile("cp.async.wait_group %0;" :: "n"(n) : "memory")

__device__ __forceinline__ void mma_f16(float* c, const uint32_t* a, const uint32_t* b) {
    asm volatile(
        "mma.sync.aligned.m16n8k16.row.col.f32.f16.f16.f32 "
        "{%0,%1,%2,%3}, {%4,%5,%6,%7}, {%8,%9}, {%0,%1,%2,%3};"
        : "+f"(c[0]), "+f"(c[1]), "+f"(c[2]), "+f"(c[3])
        : "r"(a[0]), "r"(a[1]), "r"(a[2]), "r"(a[3]), "r"(b[0]), "r"(b[1]));
}

// 128x128x128 fp16 tile compute; 8 warps in 2x4; acc accumulates.
__device__ __forceinline__ void compute_tile(float (&acc)[4][4][4],
                                             const char* a_sm, const char* b_sm,
                                             int wm, int wn, int q, int t2) {
#pragma unroll
    for (int ks = 0; ks < 8; ks++) {
        uint32_t av[4][4], bv[4][2];
#pragma unroll
        for (int mt = 0; mt < 4; mt++) {
            int off = (wm * 64 + mt * 16 + q) * SMSB + (ks * 16 + t2) * 2;
            av[mt][0] = *(const uint32_t*)(a_sm + off);
            av[mt][1] = *(const uint32_t*)(a_sm + off + 8 * SMSB);
            av[mt][2] = *(const uint32_t*)(a_sm + off + 16);
            av[mt][3] = *(const uint32_t*)(a_sm + off + 8 * SMSB + 16);
        }
#pragma unroll
        for (int nt = 0; nt < 4; nt++) {
            int off = (wn * 32 + nt * 8 + q) * SMSB + (ks * 16 + t2) * 2;
            bv[nt][0] = *(const uint32_t*)(b_sm + off);
            bv[nt][1] = *(const uint32_t*)(b_sm + off + 16);
        }
#pragma unroll
        for (int mt = 0; mt < 4; mt++)
#pragma unroll
            for (int nt = 0; nt < 4; nt++) mma_f16(acc[mt][nt], av[mt], bv[nt]);
    }
}

// A-load (rows of 128 fp32 -> fp16). ALOAD: 0 plain, 1 LN(P1=g,P2=b), 2 div-by-z(P1=z)
// STASH: also keep raw fp32 row in x_sm (row stride 512B)
template <int ALOAD, int STASH>
__device__ __forceinline__ void load_A(const float* __restrict__ A,
                                       const float* __restrict__ P1,
                                       const float* __restrict__ P2,
                                       int M, int m0, char* a_sm, char* x_sm, int tid) {
    const int lane = tid & 31;
    float4 gg, bb;
    if (ALOAD == 1) {
        gg = *(const float4*)(P1 + lane * 4);
        bb = *(const float4*)(P2 + lane * 4);
    }
#pragma unroll 4
    for (int i = tid; i < 4096; i += 256) {
        int row = i >> 5;
        float4 v = make_float4(0.f, 0.f, 0.f, 0.f);
        bool valid = (m0 + row < M);
        if (valid) v = *(const float4*)(A + (size_t)(m0 + row) * 128 + lane * 4);
        if (STASH) *(float4*)(x_sm + row * 512 + lane * 16) = v;
        if (ALOAD == 1) {
            float s = v.x + v.y + v.z + v.w;
#pragma unroll
            for (int o = 16; o; o >>= 1) s += __shfl_xor_sync(0xffffffffu, s, o);
            float mu = s * 0.0078125f;
            float d0 = v.x - mu, d1 = v.y - mu, d2 = v.z - mu, d3 = v.w - mu;
            float qq = d0 * d0 + d1 * d1 + d2 * d2 + d3 * d3;
#pragma unroll
            for (int o = 16; o; o >>= 1) qq += __shfl_xor_sync(0xffffffffu, qq, o);
            float inv = rsqrtf(qq * 0.0078125f + 1e-5f);
            v.x = d0 * inv * gg.x + bb.x;
            v.y = d1 * inv * gg.y + bb.y;
            v.z = d2 * inv * gg.z + bb.z;
            v.w = d3 * inv * gg.w + bb.w;
        } else if (ALOAD == 2) {
            float zz = valid ? P1[(size_t)(m0 + row) * 8 + (lane >> 2)] : 1.0f;
            float inv = 1.0f / (zz + 1e-6f);
            v.x *= inv; v.y *= inv; v.z *= inv; v.w *= inv;
        }
        __half2 p0 = __floats2half2_rn(v.x, v.y);
        __half2 p1 = __floats2half2_rn(v.z, v.w);
        uint2 P;
        P.x = *(const uint32_t*)&p0;
        P.y = *(const uint32_t*)&p1;
        *(uint2*)(a_sm + row * SMSB + lane * 8) = P;
    }
}

// ================= unified HMMA GEMM (K=128): C = op(A) @ Wslot =================
// EPI: 0 none, 1 +bias+residual. ALOAD: 0/1/2 as above, 3 = A is fp16 (async copy).
// OUT: 0 fp32 C, 1 fp16 C. grid.y selects B slot and C among C0/C1/C2.
template <int EPI, int ALOAD, int OUT>
__global__ __launch_bounds__(256, 2)
void mma_gemm(const void* __restrict__ Av, const float* __restrict__ P1,
              const float* __restrict__ P2, const char* __restrict__ BBase,
              void* __restrict__ C0v, void* __restrict__ C1v, void* __restrict__ C2v,
              const float* __restrict__ bias, const float* __restrict__ Rr, int M) {
    extern __shared__ char smem[];
    char* a_sm = smem;
    char* b_sm = a_sm + TILEB;
    const uint32_t sb = smem_u32(smem);
    const uint32_t sb_b = sb + TILEB;

    const int tid = threadIdx.x, wid = tid >> 5, lane = tid & 31;
    const int wm = wid >> 2, wn = wid & 3;
    const int q = lane >> 2, t2 = (lane & 3) * 2;
    const int m0 = blockIdx.x * 128;
    const char* Bg = BBase + (size_t)blockIdx.y * 81920;
    void* Cv = (blockIdx.y == 0) ? C0v : (blockIdx.y == 1) ? C1v : C2v;

    // async B image copy
    for (int i = tid * 16; i < TILEB; i += 4096) cpa16(sb_b + i, Bg + i);
    // ALOAD==3: A already fp16 [row][128] (256B rows) -> async copy into a_sm
    if (ALOAD == 3) {
        const char* Ah = (const char*)Av;
        for (int i = tid; i < 2048; i += 256) {
            int row = i >> 4, j = i & 15;
            if (m0 + row < M)
                cpa16(sb + row * SMSB + j * 16, Ah + (size_t)(m0 + row) * 256 + j * 16);
        }
    }
    CPA_COMMIT();

    float acc[4][4][4];
#pragma unroll
    for (int mt = 0; mt < 4; mt++)
#pragma unroll
        for (int nt = 0; nt < 4; nt++)
#pragma unroll
            for (int j = 0; j < 4; j++) acc[mt][nt][j] = 0.0f;

    if (ALOAD != 3)
        load_A<ALOAD, 0>((const float*)Av, P1, P2, M, m0, a_sm, nullptr, tid);
    CPA_WAIT(0);
    __syncthreads();
    compute_tile(acc, a_sm, b_sm, wm, wn, q, t2);

#pragma unroll
    for (int mt = 0; mt < 4; mt++) {
#pragma unroll
        for (int half = 0; half < 2; half++) {
            int row = m0 + wm * 64 + mt * 16 + q + half * 8;
            if (row >= M) continue;
#pragma unroll
            for (int nt = 0; nt < 4; nt++) {
                int col = wn * 32 + nt * 8 + t2;
                float o0 = acc[mt][nt][half * 2 + 0];
                float o1 = acc[mt][nt][half * 2 + 1];
                if (EPI == 1) {
                    float2 bbv = *(const float2*)(bias + col);
                    float2 rr = *(const float2*)(Rr + (size_t)row * 128 + col);
                    o0 += bbv.x + rr.x;
                    o1 += bbv.y + rr.y;
                }
                if (OUT == 0) {
                    *(float2*)((float*)Cv + (size_t)row * 128 + col) = make_float2(o0, o1);
                } else {
                    __half2 hp = __floats2half2_rn(o0, o1);
                    *(uint32_t*)((char*)Cv + ((size_t)row * 128 + col) * 2) =
                        *(const uint32_t*)&hp;
                }
            }
        }
    }
}

// ============ fused FFN: out = x + silu(LN(x)@W1) @ W2, per 128-row tile ============
__global__ __launch_bounds__(256, 1)
void ffn_fused(const float* __restrict__ X, const char* __restrict__ W1,
               const char* __restrict__ W2, const float* __restrict__ g,
               const float* __restrict__ b, float* __restrict__ out, int M) {
    extern __shared__ char smem[];
    char* a_sm = smem;
    char* w0 = a_sm + TILEB;
    char* w1 = w0 + TILEB;
    char* t_sm = w1 + TILEB;
    char* x_sm = t_sm + TILEB;  // fp32 X tile stash, 64KB
    const uint32_t sb = smem_u32(smem);
    const uint32_t s_w0 = sb + TILEB, s_w1 = s_w0 + TILEB;

    const int tid = threadIdx.x, wid = tid >> 5, lane = tid & 31;
    const int wm = wid >> 2, wn = wid & 3;
    const int q = lane >> 2, t2 = (lane & 3) * 2;
    const int m0 = blockIdx.x * 128;

    // G0: W1 half0 -> w0
    for (int i = tid * 16; i < TILEB; i += 4096) cpa16(s_w0 + i, W1 + i);
    CPA_COMMIT();
    // G1: W2 chunk0 -> w1 (rows of 528B, first 256B slice)
    for (int i = tid; i < 128 * 16; i += 256) {
        int n = i >> 4, j = i & 15;
        cpa16(s_w1 + n * SMSB + j * 16, W2 + (size_t)n * 528 + j * 16);
    }
    CPA_COMMIT();

    load_A<1, 1>(X, g, b, M, m0, a_sm, x_sm, tid);

    float acc2[4][4][4];
#pragma unroll
    for (int mt = 0; mt < 4; mt++)
#pragma unroll
        for (int nt = 0; nt < 4; nt++)
#pragma unroll
            for (int j = 0; j < 4; j++) acc2[mt][nt][j] = 0.0f;

    float acc1[4][4][4];
#pragma unroll
    for (int h = 0; h < 2; h++) {
        CPA_WAIT(1);
        __syncthreads();
#pragma unroll
        for (int mt = 0; mt < 4; mt++)
#pragma unroll
            for (int nt = 0; nt < 4; nt++)
#pragma unroll
                for (int j = 0; j < 4; j++) acc1[mt][nt][j] = 0.0f;
        compute_tile(acc1, a_sm, w0, wm, wn, q, t2);
        __syncthreads();
        if (h == 0) {
            for (int i = tid * 16; i < TILEB; i += 4096) cpa16(s_w0 + i, W1 + TILEB + i);
            CPA_COMMIT();
        }
        // silu + fp16 -> t
#pragma unroll
        for (int mt = 0; mt < 4; mt++)
#pragma unroll
            for (int nt = 0; nt < 4; nt++) {
                int row0 = wm * 64 + mt * 16 + q;
                int col = wn * 32 + nt * 8 + t2;
#pragma unroll
                for (int half = 0; half < 2; half++) {
                    float s0 = acc1[mt][nt][half * 2 + 0];
                    float s1 = acc1[mt][nt][half * 2 + 1];
                    s0 = s0 / (1.0f + expf(-s0));
                    s1 = s1 / (1.0f + expf(-s1));
                    __half2 p = __floats2half2_rn(s0, s1);
                    *(uint32_t*)(t_sm + (row0 + half * 8) * SMSB + col * 2) =
                        *(const uint32_t*)&p;
                }
            }
        if (h == 0) CPA_WAIT(1); else CPA_WAIT(0);
        __syncthreads();
        compute_tile(acc2, t_sm, w1, wm, wn, q, t2);
        __syncthreads();
        if (h == 0) {
            for (int i = tid; i < 128 * 16; i += 256) {
                int n = i >> 4, j = i & 15;
                cpa16(s_w1 + n * SMSB + j * 16, W2 + (size_t)n * 528 + 256 + j * 16);
            }
            CPA_COMMIT();
        }
    }

    // epilogue: + residual from smem stash
#pragma unroll
    for (int mt = 0; mt < 4; mt++) {
#pragma unroll
        for (int half = 0; half < 2; half++) {
            int lrow = wm * 64 + mt * 16 + q + half * 8;
            int row = m0 + lrow;
            if (row >= M) continue;
#pragma unroll
            for (int nt = 0; nt < 4; nt++) {
                int col = wn * 32 + nt * 8 + t2;
                float2 rr = *(const float2*)(x_sm + lrow * 512 + col * 4);
                float o0 = acc2[mt][nt][half * 2 + 0] + rr.x;
                float o1 = acc2[mt][nt][half * 2 + 1] + rr.y;
                *(float2*)(out + (size_t)row * 128 + col) = make_float2(o0, o1);
            }
        }
    }
}

// ====== weight prep: all 10 weights, fp16, one launch ======
__global__ void prep_all(const float* w0, const float* w1, const float* w2,
                         const float* w3, const float* w4, const float* w5,
                         const float* w6, const float* w7, const float* w8,
                         const float* w9, char* __restrict__ ib) {
    int y = blockIdx.y;
    const float* W;
    int K = 128, N = 128;
    switch (y) {
        case 0: W = w0; break;
        case 1: W = w1; break;
        case 2: W = w2; break;
        case 3: W = w3; break;
        case 4: W = w4; break;
        case 5: W = w5; break;
        case 6: W = w6; N = 256; break;
        case 7: W = w7; N = 256; break;
        case 8: W = w8; K = 256; break;
        default: W = w9; K = 256; break;
    }
    int idx = blockIdx.x * 256 + threadIdx.x;
    if (idx >= K * N) return;
    int k = idx / N, n = idx % N;
    size_t off = (size_t)y * 81920 + ((size_t)n * (K + 8) + k) * 2;
    *(unsigned short*)(ib + off) = __half_as_ushort(__float2half_rn(W[idx]));
}

// ================= per-edge attention (one warp per edge, fp16 tensors) =================
__global__ void edge_kernel(const __half* __restrict__ Q, const __half* __restrict__ K,
                            const __half* __restrict__ V, __half* __restrict__ PE,
                            const int* __restrict__ eidx, float* __restrict__ wV,
                            float* __restrict__ z, int E) {
    int e = blockIdx.x * 8 + (threadIdx.x >> 5);
    if (e >= E) return;
    int lane = threadIdx.x & 31;
    int src = eidx[e];
    int dst = eidx[E + e];
    int i = lane * 4;
    uint2 ku = *(const uint2*)(K + (size_t)src * 128 + i);
    uint2 qu = *(const uint2*)(Q + (size_t)dst * 128 + i);
    uint2 pu = *(const uint2*)(PE + (size_t)e * 128 + i);
    float2 k0 = __half22float2(*(__half2*)&ku.x), k1 = __half22float2(*(__half2*)&ku.y);
    float2 q0 = __half22float2(*(__half2*)&qu.x), q1 = __half22float2(*(__half2*)&qu.y);
    float2 p0 = __half22float2(*(__half2*)&pu.x), p1 = __half22float2(*(__half2*)&pu.y);
    const float sc = 0.25f;
    float s0 = fminf(fmaxf(k0.x * q0.x * sc, -5.0f), 5.0f) * p0.x;
    float s1 = fminf(fmaxf(k0.y * q0.y * sc, -5.0f), 5.0f) * p0.y;
    float s2 = fminf(fmaxf(k1.x * q1.x * sc, -5.0f), 5.0f) * p1.x;
    float s3 = fminf(fmaxf(k1.y * q1.y * sc, -5.0f), 5.0f) * p1.y;
    __half2 e0 = __floats2half2_rn(s0, s1), e1 = __floats2half2_rn(s2, s3);
    uint2 eo;
    eo.x = *(const uint32_t*)&e0;
    eo.y = *(const uint32_t*)&e1;
    *(uint2*)(PE + (size_t)e * 128 + i) = eo;

    float hs = s0 + s1 + s2 + s3;
    hs += __shfl_xor_sync(0xffffffffu, hs, 1);
    hs += __shfl_xor_sync(0xffffffffu, hs, 2);
    float w = expf(fminf(fmaxf(hs, -5.0f), 5.0f));

    uint2 vu = *(const uint2*)(V + (size_t)src * 128 + i);
    float2 v0 = __half22float2(*(__half2*)&vu.x), v1 = __half22float2(*(__half2*)&vu.y);
    float* base = wV + (size_t)dst * 128 + i;
    atomicAdd(base + 0, v0.x * w);
    atomicAdd(base + 1, v0.y * w);
    atomicAdd(base + 2, v1.x * w);
    atomicAdd(base + 3, v1.y * w);
    if ((lane & 3) == 0) atomicAdd(z + (size_t)dst * 8 + (lane >> 2), w);
}

__global__ void zero2_kernel(float* __restrict__ a, size_t na,
                             float* __restrict__ bz, size_t nb) {
    size_t i = (size_t)blockIdx.x * blockDim.x + threadIdx.x;
    size_t st = (size_t)gridDim.x * blockDim.x;
    for (size_t k = i; k < na; k += st) a[k] = 0.0f;
    for (size_t k = i; k < nb; k += st) bz[k] = 0.0f;
}

// ================= launch =================
extern "C" void kernel_launch(void* const* d_in, const int* in_sizes, int n_in,
                              void* d_out, int out_size) {
    const float* node = (const float*)d_in[0];
    const float* edge = (const float*)d_in[1];
    const int*   eidx = (const int*)d_in[2];
    const float* Wq = (const float*)d_in[3];
    const float* Wk = (const float*)d_in[4];
    const float* Wv = (const float*)d_in[5];
    const float* We = (const float*)d_in[6];
    const float* Wo_n = (const float*)d_in[7];
    const float* bo_n = (const float*)d_in[8];
    const float* Wo_e = (const float*)d_in[9];
    const float* bo_e = (const float*)d_in[10];
    const float* W1n = (const float*)d_in[11];
    const float* W2n = (const float*)d_in[12];
    const float* W1e = (const float*)d_in[13];
    const float* W2e = (const float*)d_in[14];
    const float* g1n = (const float*)d_in[15];
    const float* b1n = (const float*)d_in[16];
    const float* g1e = (const float*)d_in[17];
    const float* b1e = (const float*)d_in[18];
    const float* g2n = (const float*)d_in[19];
    const float* b2n = (const float*)d_in[20];
    const float* g2e = (const float*)d_in[21];
    const float* b2e = (const float*)d_in[22];

    const int N = in_sizes[0] / 128;
    const int E = in_sizes[1] / 128;
    float* out = (float*)d_out;

    __half *Q, *Kb, *Vb, *PE;
    float *wV, *z, *h2, *e2;
    char* wim;
    cudaGetSymbolAddress((void**)&Q, g_Q);
    cudaGetSymbolAddress((void**)&Kb, g_Kb);
    cudaGetSymbolAddress((void**)&Vb, g_Vb);
    cudaGetSymbolAddress((void**)&PE, g_PE);
    cudaGetSymbolAddress((void**)&wV, g_wV);
    cudaGetSymbolAddress((void**)&z, g_z);
    cudaGetSymbolAddress((void**)&h2, g_h2);
    cudaGetSymbolAddress((void**)&e2, g_e2);
    cudaGetSymbolAddress((void**)&wim, g_wimg);

    auto IM = [&](int i) { return wim + (size_t)i * 81920; };

    const int SMG = 2 * TILEB;           // 69632
    const int SMF = 4 * TILEB + 65536;   // 204800
    cudaFuncSetAttribute((const void*)mma_gemm<0, 1, 1>, cudaFuncAttributeMaxDynamicSharedMemorySize, SMG);
    cudaFuncSetAttribute((const void*)mma_gemm<1, 2, 0>, cudaFuncAttributeMaxDynamicSharedMemorySize, SMG);
    cudaFuncSetAttribute((const void*)mma_gemm<1, 3, 0>, cudaFuncAttributeMaxDynamicSharedMemorySize, SMG);
    cudaFuncSetAttribute((const void*)ffn_fused, cudaFuncAttributeMaxDynamicSharedMemorySize, SMF);

    const int TtN = (N + 127) / 128;
    const int TtE = (E + 127) / 128;

    // 0) all weight images in one launch
    prep_all<<<dim3(128, 10), 256>>>(Wq, Wk, Wv, We, Wo_n, Wo_e, W1n, W1e, W2n, W2e, wim);

    // 1) fused LN1 + QKV projections (fp16 out; grid.y = slot 0/1/2)
    mma_gemm<0, 1, 1><<<dim3(TtN, 3), 256, SMG>>>(node, g1n, b1n, IM(0),
                                                  Q, Kb, Vb, nullptr, nullptr, N);
    // 2) fused LN1e + PE projection (fp16 out)
    mma_gemm<0, 1, 1><<<dim3(TtE, 1), 256, SMG>>>(edge, g1e, b1e, IM(3),
                                                  PE, PE, PE, nullptr, nullptr, E);

    // 3) attention aggregation
    zero2_kernel<<<2048, 256>>>(wV, (size_t)N * 128, z, (size_t)N * 8);
    edge_kernel<<<(E + 7) / 8, 256>>>(Q, Kb, Vb, PE, eidx, wV, z, E);

    // 4) output projections (+ bias + residual)
    mma_gemm<1, 2, 0><<<dim3(TtN, 1), 256, SMG>>>(wV, z, nullptr, IM(4),
                                                  h2, h2, h2, bo_n, node, N);
    mma_gemm<1, 3, 0><<<dim3(TtE, 1), 256, SMG>>>(PE, nullptr, nullptr, IM(5),
                                                  e2, e2, e2, bo_e, edge, E);

    // 5) fused LN2 + FFN + residual
    ffn_fused<<<TtN, 256, SMF>>>(h2, IM(6), IM(8), g2n, b2n, out, N);
    ffn_fused<<<TtE, 256, SMF>>>(e2, IM(7), IM(9), g2e, b2e,
                                 out + (size_t)N * 128, E);
}

// round 8
// speedup vs baseline: 4.4568x; 1.1284x over previous
#include <cuda_runtime.h>
#include <cuda_fp16.h>
#include <math.h>
#include <stdint.h>

// ================= scratch (device globals) =================
#define NMAX 50000
#define EMAX 400000

__device__ __half g_Q [(size_t)NMAX * 128];
__device__ __half g_Kb[(size_t)NMAX * 128];
__device__ __half g_Vb[(size_t)NMAX * 128];
__device__ __half g_PE[(size_t)EMAX * 128];   // PE -> overwritten with e_attn
__device__ float g_wV [(size_t)NMAX * 128];
__device__ float g_z  [(size_t)NMAX * 8];
// weight images: [n][k] fp16, k padded by 8; 10 slots x 80KB
__device__ char g_wimg[10][81920];

#define SMSB 272  // smem k-stride in bytes (136 fp16)
#define TILEB (128 * SMSB)

// ================= PTX helpers =================
__device__ __forceinline__ uint32_t smem_u32(const void* p) {
    uint32_t a;
    asm("{ .reg .u64 t; cvta.to.shared.u64 t, %1; cvt.u32.u64 %0, t; }" : "=r"(a) : "l"(p));
    return a;
}
__device__ __forceinline__ void cpa16(uint32_t d, const void* s) {
    asm volatile("cp.async.cg.shared.global [%0], [%1], 16;" :: "r"(d), "l"(s));
}
#define CPA_COMMIT() asm volatile("cp.async.commit_group;" ::: "memory")
#define CPA_WAIT(n)  asm volatile("cp.async.wait_group %0;" :: "n"(n) : "memory")

__device__ __forceinline__ void red_add_v4(float* p, float a, float b, float c, float d) {
    asm volatile("red.global.add.v4.f32 [%0], {%1, %2, %3, %4};"
                 :: "l"(p), "f"(a), "f"(b), "f"(c), "f"(d) : "memory");
}

__device__ __forceinline__ void mma_f16(float* c, const uint32_t* a, const uint32_t* b) {
    asm volatile(
        "mma.sync.aligned.m16n8k16.row.col.f32.f16.f16.f32 "
        "{%0,%1,%2,%3}, {%4,%5,%6,%7}, {%8,%9}, {%0,%1,%2,%3};"
        : "+f"(c[0]), "+f"(c[1]), "+f"(c[2]), "+f"(c[3])
        : "r"(a[0]), "r"(a[1]), "r"(a[2]), "r"(a[3]), "r"(b[0]), "r"(b[1]));
}

// 128x128x128 fp16 tile compute; 8 warps in 2x4; acc accumulates.
__device__ __forceinline__ void compute_tile(float (&acc)[4][4][4],
                                             const char* a_sm, const char* b_sm,
                                             int wm, int wn, int q, int t2) {
#pragma unroll
    for (int ks = 0; ks < 8; ks++) {
        uint32_t av[4][4], bv[4][2];
#pragma unroll
        for (int mt = 0; mt < 4; mt++) {
            int off = (wm * 64 + mt * 16 + q) * SMSB + (ks * 16 + t2) * 2;
            av[mt][0] = *(const uint32_t*)(a_sm + off);
            av[mt][1] = *(const uint32_t*)(a_sm + off + 8 * SMSB);
            av[mt][2] = *(const uint32_t*)(a_sm + off + 16);
            av[mt][3] = *(const uint32_t*)(a_sm + off + 8 * SMSB + 16);
        }
#pragma unroll
        for (int nt = 0; nt < 4; nt++) {
            int off = (wn * 32 + nt * 8 + q) * SMSB + (ks * 16 + t2) * 2;
            bv[nt][0] = *(const uint32_t*)(b_sm + off);
            bv[nt][1] = *(const uint32_t*)(b_sm + off + 16);
        }
#pragma unroll
        for (int mt = 0; mt < 4; mt++)
#pragma unroll
            for (int nt = 0; nt < 4; nt++) mma_f16(acc[mt][nt], av[mt], bv[nt]);
    }
}

// A-load (rows of 128 fp32 -> fp16). ALOAD: 1 LN(P1=g,P2=b), 2 div-by-z(P1=z)
template <int ALOAD>
__device__ __forceinline__ void load_A(const float* __restrict__ A,
                                       const float* __restrict__ P1,
                                       const float* __restrict__ P2,
                                       int M, int m0, char* a_sm, int tid) {
    const int lane = tid & 31;
    float4 gg, bb;
    if (ALOAD == 1) {
        gg = *(const float4*)(P1 + lane * 4);
        bb = *(const float4*)(P2 + lane * 4);
    }
#pragma unroll 4
    for (int i = tid; i < 4096; i += 256) {
        int row = i >> 5;
        float4 v = make_float4(0.f, 0.f, 0.f, 0.f);
        bool valid = (m0 + row < M);
        if (valid) v = *(const float4*)(A + (size_t)(m0 + row) * 128 + lane * 4);
        if (ALOAD == 1) {
            float s = v.x + v.y + v.z + v.w;
#pragma unroll
            for (int o = 16; o; o >>= 1) s += __shfl_xor_sync(0xffffffffu, s, o);
            float mu = s * 0.0078125f;
            float d0 = v.x - mu, d1 = v.y - mu, d2 = v.z - mu, d3 = v.w - mu;
            float qq = d0 * d0 + d1 * d1 + d2 * d2 + d3 * d3;
#pragma unroll
            for (int o = 16; o; o >>= 1) qq += __shfl_xor_sync(0xffffffffu, qq, o);
            float inv = rsqrtf(qq * 0.0078125f + 1e-5f);
            v.x = d0 * inv * gg.x + bb.x;
            v.y = d1 * inv * gg.y + bb.y;
            v.z = d2 * inv * gg.z + bb.z;
            v.w = d3 * inv * gg.w + bb.w;
        } else if (ALOAD == 2) {
            float zz = valid ? P1[(size_t)(m0 + row) * 8 + (lane >> 2)] : 1.0f;
            float inv = 1.0f / (zz + 1e-6f);
            v.x *= inv; v.y *= inv; v.z *= inv; v.w *= inv;
        }
        __half2 p0 = __floats2half2_rn(v.x, v.y);
        __half2 p1 = __floats2half2_rn(v.z, v.w);
        uint2 P;
        P.x = *(const uint32_t*)&p0;
        P.y = *(const uint32_t*)&p1;
        *(uint2*)(a_sm + row * SMSB + lane * 8) = P;
    }
}

// ================= QKV/PE GEMM (K=128): fp16 C = LN(A) @ Wslot =================
__global__ __launch_bounds__(256, 2)
void mma_gemm_ln(const float* __restrict__ A, const float* __restrict__ g,
                 const float* __restrict__ b, const char* __restrict__ BBase,
                 __half* __restrict__ C0, __half* __restrict__ C1,
                 __half* __restrict__ C2, int M) {
    extern __shared__ char smem[];
    char* a_sm = smem;
    char* b_sm = a_sm + TILEB;
    const uint32_t sb_b = smem_u32(smem) + TILEB;

    const int tid = threadIdx.x, wid = tid >> 5, lane = tid & 31;
    const int wm = wid >> 2, wn = wid & 3;
    const int q = lane >> 2, t2 = (lane & 3) * 2;
    const int m0 = blockIdx.x * 128;
    const char* Bg = BBase + (size_t)blockIdx.y * 81920;
    __half* C = (blockIdx.y == 0) ? C0 : (blockIdx.y == 1) ? C1 : C2;

    for (int i = tid * 16; i < TILEB; i += 4096) cpa16(sb_b + i, Bg + i);
    CPA_COMMIT();

    float acc[4][4][4];
#pragma unroll
    for (int mt = 0; mt < 4; mt++)
#pragma unroll
        for (int nt = 0; nt < 4; nt++)
#pragma unroll
            for (int j = 0; j < 4; j++) acc[mt][nt][j] = 0.0f;

    load_A<1>(A, g, b, M, m0, a_sm, tid);
    CPA_WAIT(0);
    __syncthreads();
    compute_tile(acc, a_sm, b_sm, wm, wn, q, t2);

#pragma unroll
    for (int mt = 0; mt < 4; mt++) {
#pragma unroll
        for (int half = 0; half < 2; half++) {
            int row = m0 + wm * 64 + mt * 16 + q + half * 8;
            if (row >= M) continue;
#pragma unroll
            for (int nt = 0; nt < 4; nt++) {
                int col = wn * 32 + nt * 8 + t2;
                __half2 hp = __floats2half2_rn(acc[mt][nt][half * 2 + 0],
                                               acc[mt][nt][half * 2 + 1]);
                *(uint32_t*)((char*)C + ((size_t)row * 128 + col) * 2) =
                    *(const uint32_t*)&hp;
            }
        }
    }
}

// ====== fused output chain: out = e2 + FFN(LN2(e2)),  e2 = R + bias + op(A)@Wo ======
// ALOADA: 3 = A fp16 (e_attn), 2 = A fp32 wV with z-divide (P1=z)
template <int ALOADA>
__global__ __launch_bounds__(256, 1)
void out_ffn(const void* __restrict__ Av, const float* __restrict__ P1,
             const char* __restrict__ Wo, const float* __restrict__ bias,
             const float* __restrict__ R, const char* __restrict__ W1,
             const char* __restrict__ W2, const float* __restrict__ g,
             const float* __restrict__ b, float* __restrict__ out, int M) {
    extern __shared__ char smem[];
    char* a_sm = smem;
    char* w0 = a_sm + TILEB;
    char* w1 = w0 + TILEB;
    char* t_sm = w1 + TILEB;
    char* x_sm = t_sm + TILEB;  // fp32 residual/e2 stash, 512B rows
    const uint32_t sb = smem_u32(smem);
    const uint32_t s_w0 = sb + TILEB, s_w1 = s_w0 + TILEB;
    const uint32_t s_x = sb + 4 * TILEB;

    const int tid = threadIdx.x, wid = tid >> 5, lane = tid & 31;
    const int wm = wid >> 2, wn = wid & 3;
    const int q = lane >> 2, t2 = (lane & 3) * 2;
    const int m0 = blockIdx.x * 128;

    // G0: Wo -> w0, R -> x_sm, (fp16 A -> a_sm)
    for (int i = tid * 16; i < TILEB; i += 4096) cpa16(s_w0 + i, Wo + i);
    for (int i = tid; i < 128 * 32; i += 256) {
        int row = i >> 5, j = i & 31;
        if (m0 + row < M)
            cpa16(s_x + row * 512 + j * 16, (const char*)R + ((size_t)(m0 + row) * 512 + j * 16));
    }
    if (ALOADA == 3) {
        const char* Ah = (const char*)Av;
        for (int i = tid; i < 128 * 16; i += 256) {
            int row = i >> 4, j = i & 15;
            if (m0 + row < M)
                cpa16(sb + row * SMSB + j * 16, Ah + (size_t)(m0 + row) * 256 + j * 16);
        }
    }
    CPA_COMMIT();
    // G1: W1 half0 -> w1
    for (int i = tid * 16; i < TILEB; i += 4096) cpa16(s_w1 + i, W1 + i);
    CPA_COMMIT();

    if (ALOADA == 2) load_A<2>((const float*)Av, P1, nullptr, M, m0, a_sm, tid);

    float acc1[4][4][4];
#pragma unroll
    for (int mt = 0; mt < 4; mt++)
#pragma unroll
        for (int nt = 0; nt < 4; nt++)
#pragma unroll
            for (int j = 0; j < 4; j++) acc1[mt][nt][j] = 0.0f;

    CPA_WAIT(1);  // G0 done
    __syncthreads();
    compute_tile(acc1, a_sm, w0, wm, wn, q, t2);  // op(A) @ Wo
    __syncthreads();
    // G2: W2 chunk0 -> w0
    for (int i = tid; i < 128 * 16; i += 256) {
        int n = i >> 4, j = i & 15;
        cpa16(s_w0 + n * SMSB + j * 16, W2 + (size_t)n * 528 + j * 16);
    }
    CPA_COMMIT();

    // e2 tile into x_sm: x += acc + bias
#pragma unroll
    for (int mt = 0; mt < 4; mt++)
#pragma unroll
        for (int half = 0; half < 2; half++) {
            int lrow = wm * 64 + mt * 16 + q + half * 8;
#pragma unroll
            for (int nt = 0; nt < 4; nt++) {
                int col = wn * 32 + nt * 8 + t2;
                float2 bbv = *(const float2*)(bias + col);
                float2 xx = *(const float2*)(x_sm + lrow * 512 + col * 4);
                xx.x += acc1[mt][nt][half * 2 + 0] + bbv.x;
                xx.y += acc1[mt][nt][half * 2 + 1] + bbv.y;
                *(float2*)(x_sm + lrow * 512 + col * 4) = xx;
            }
        }
    __syncthreads();

    // LN2 over x_sm rows -> a_sm (fp16)
    {
        float4 gg = *(const float4*)(g + lane * 4);
        float4 bb = *(const float4*)(b + lane * 4);
#pragma unroll 4
        for (int i = tid; i < 4096; i += 256) {
            int row = i >> 5;
            float4 v = *(const float4*)(x_sm + row * 512 + lane * 16);
            float s = v.x + v.y + v.z + v.w;
#pragma unroll
            for (int o = 16; o; o >>= 1) s += __shfl_xor_sync(0xffffffffu, s, o);
            float mu = s * 0.0078125f;
            float d0 = v.x - mu, d1 = v.y - mu, d2 = v.z - mu, d3 = v.w - mu;
            float qq = d0 * d0 + d1 * d1 + d2 * d2 + d3 * d3;
#pragma unroll
            for (int o = 16; o; o >>= 1) qq += __shfl_xor_sync(0xffffffffu, qq, o);
            float inv = rsqrtf(qq * 0.0078125f + 1e-5f);
            __half2 p0 = __floats2half2_rn(d0 * inv * gg.x + bb.x, d1 * inv * gg.y + bb.y);
            __half2 p1 = __floats2half2_rn(d2 * inv * gg.z + bb.z, d3 * inv * gg.w + bb.w);
            uint2 P;
            P.x = *(const uint32_t*)&p0;
            P.y = *(const uint32_t*)&p1;
            *(uint2*)(a_sm + row * SMSB + lane * 8) = P;
        }
    }
    __syncthreads();

    float acc2[4][4][4];
#pragma unroll
    for (int mt = 0; mt < 4; mt++)
#pragma unroll
        for (int nt = 0; nt < 4; nt++)
#pragma unroll
            for (int j = 0; j < 4; j++) acc2[mt][nt][j] = 0.0f;

#pragma unroll
    for (int h = 0; h < 2; h++) {
        CPA_WAIT(1);  // h=0: G1 (w1=W1h0); h=1: G3 (w1=W1h1)
        __syncthreads();
#pragma unroll
        for (int mt = 0; mt < 4; mt++)
#pragma unroll
            for (int nt = 0; nt < 4; nt++)
#pragma unroll
                for (int j = 0; j < 4; j++) acc1[mt][nt][j] = 0.0f;
        compute_tile(acc1, a_sm, w1, wm, wn, q, t2);
        __syncthreads();
        if (h == 0) {
            // G3: W1 half1 -> w1
            for (int i = tid * 16; i < TILEB; i += 4096) cpa16(s_w1 + i, W1 + TILEB + i);
            CPA_COMMIT();
        }
        // silu -> t_sm (fp16)
#pragma unroll
        for (int mt = 0; mt < 4; mt++)
#pragma unroll
            for (int nt = 0; nt < 4; nt++) {
                int row0 = wm * 64 + mt * 16 + q;
                int col = wn * 32 + nt * 8 + t2;
#pragma unroll
                for (int half = 0; half < 2; half++) {
                    float s0 = acc1[mt][nt][half * 2 + 0];
                    float s1 = acc1[mt][nt][half * 2 + 1];
                    s0 = s0 / (1.0f + expf(-s0));
                    s1 = s1 / (1.0f + expf(-s1));
                    __half2 p = __floats2half2_rn(s0, s1);
                    *(uint32_t*)(t_sm + (row0 + half * 8) * SMSB + col * 2) =
                        *(const uint32_t*)&p;
                }
            }
        if (h == 0) CPA_WAIT(1); else CPA_WAIT(0);  // W2 chunk in w0
        __syncthreads();
        compute_tile(acc2, t_sm, w0, wm, wn, q, t2);
        __syncthreads();
        if (h == 0) {
            // G4: W2 chunk1 -> w0
            for (int i = tid; i < 128 * 16; i += 256) {
                int n = i >> 4, j = i & 15;
                cpa16(s_w0 + n * SMSB + j * 16, W2 + (size_t)n * 528 + 256 + j * 16);
            }
            CPA_COMMIT();
        }
    }

    // epilogue: out = x_sm (e2) + acc2
#pragma unroll
    for (int mt = 0; mt < 4; mt++) {
#pragma unroll
        for (int half = 0; half < 2; half++) {
            int lrow = wm * 64 + mt * 16 + q + half * 8;
            int row = m0 + lrow;
            if (row >= M) continue;
#pragma unroll
            for (int nt = 0; nt < 4; nt++) {
                int col = wn * 32 + nt * 8 + t2;
                float2 rr = *(const float2*)(x_sm + lrow * 512 + col * 4);
                float o0 = acc2[mt][nt][half * 2 + 0] + rr.x;
                float o1 = acc2[mt][nt][half * 2 + 1] + rr.y;
                *(float2*)(out + (size_t)row * 128 + col) = make_float2(o0, o1);
            }
        }
    }
}

// ====== weight prep: all 10 weights, fp16, one launch ======
__global__ void prep_all(const float* w0, const float* w1, const float* w2,
                         const float* w3, const float* w4, const float* w5,
                         const float* w6, const float* w7, const float* w8,
                         const float* w9, char* __restrict__ ib) {
    int y = blockIdx.y;
    const float* W;
    int K = 128, N = 128;
    switch (y) {
        case 0: W = w0; break;
        case 1: W = w1; break;
        case 2: W = w2; break;
        case 3: W = w3; break;
        case 4: W = w4; break;
        case 5: W = w5; break;
        case 6: W = w6; N = 256; break;
        case 7: W = w7; N = 256; break;
        case 8: W = w8; K = 256; break;
        default: W = w9; K = 256; break;
    }
    int idx = blockIdx.x * 256 + threadIdx.x;
    if (idx >= K * N) return;
    int k = idx / N, n = idx % N;
    size_t off = (size_t)y * 81920 + ((size_t)n * (K + 8) + k) * 2;
    *(unsigned short*)(ib + off) = __half_as_ushort(__float2half_rn(W[idx]));
}

// ================= per-edge attention (one warp per edge, fp16 tensors) =================
__global__ void edge_kernel(const __half* __restrict__ Q, const __half* __restrict__ K,
                            const __half* __restrict__ V, __half* __restrict__ PE,
                            const int* __restrict__ eidx, float* __restrict__ wV,
                            float* __restrict__ z, int E) {
    int e = blockIdx.x * 8 + (threadIdx.x >> 5);
    if (e >= E) return;
    int lane = threadIdx.x & 31;
    int src = eidx[e];
    int dst = eidx[E + e];
    int i = lane * 4;
    uint2 ku = *(const uint2*)(K + (size_t)src * 128 + i);
    uint2 qu = *(const uint2*)(Q + (size_t)dst * 128 + i);
    uint2 pu = *(const uint2*)(PE + (size_t)e * 128 + i);
    float2 k0 = __half22float2(*(__half2*)&ku.x), k1 = __half22float2(*(__half2*)&ku.y);
    float2 q0 = __half22float2(*(__half2*)&qu.x), q1 = __half22float2(*(__half2*)&qu.y);
    float2 p0 = __half22float2(*(__half2*)&pu.x), p1 = __half22float2(*(__half2*)&pu.y);
    const float sc = 0.25f;
    float s0 = fminf(fmaxf(k0.x * q0.x * sc, -5.0f), 5.0f) * p0.x;
    float s1 = fminf(fmaxf(k0.y * q0.y * sc, -5.0f), 5.0f) * p0.y;
    float s2 = fminf(fmaxf(k1.x * q1.x * sc, -5.0f), 5.0f) * p1.x;
    float s3 = fminf(fmaxf(k1.y * q1.y * sc, -5.0f), 5.0f) * p1.y;
    __half2 e0 = __floats2half2_rn(s0, s1), e1 = __floats2half2_rn(s2, s3);
    uint2 eo;
    eo.x = *(const uint32_t*)&e0;
    eo.y = *(const uint32_t*)&e1;
    *(uint2*)(PE + (size_t)e * 128 + i) = eo;

    float hs = s0 + s1 + s2 + s3;
    hs += __shfl_xor_sync(0xffffffffu, hs, 1);
    hs += __shfl_xor_sync(0xffffffffu, hs, 2);
    float w = expf(fminf(fmaxf(hs, -5.0f), 5.0f));

    uint2 vu = *(const uint2*)(V + (size_t)src * 128 + i);
    float2 v0 = __half22float2(*(__half2*)&vu.x), v1 = __half22float2(*(__half2*)&vu.y);
    red_add_v4(wV + (size_t)dst * 128 + i, v0.x * w, v0.y * w, v1.x * w, v1.y * w);
    if ((lane & 3) == 0)
        asm volatile("red.global.add.f32 [%0], %1;"
                     :: "l"(z + (size_t)dst * 8 + (lane >> 2)), "f"(w) : "memory");
}

__global__ void zero2_kernel(float* __restrict__ a, size_t na,
                             float* __restrict__ bz, size_t nb) {
    size_t i = (size_t)blockIdx.x * blockDim.x + threadIdx.x;
    size_t st = (size_t)gridDim.x * blockDim.x;
    for (size_t k = i; k < na; k += st) a[k] = 0.0f;
    for (size_t k = i; k < nb; k += st) bz[k] = 0.0f;
}

// ================= launch =================
extern "C" void kernel_launch(void* const* d_in, const int* in_sizes, int n_in,
                              void* d_out, int out_size) {
    const float* node = (const float*)d_in[0];
    const float* edge = (const float*)d_in[1];
    const int*   eidx = (const int*)d_in[2];
    const float* Wq = (const float*)d_in[3];
    const float* Wk = (const float*)d_in[4];
    const float* Wv = (const float*)d_in[5];
    const float* We = (const float*)d_in[6];
    const float* Wo_n = (const float*)d_in[7];
    const float* bo_n = (const float*)d_in[8];
    const float* Wo_e = (const float*)d_in[9];
    const float* bo_e = (const float*)d_in[10];
    const float* W1n = (const float*)d_in[11];
    const float* W2n = (const float*)d_in[12];
    const float* W1e = (const float*)d_in[13];
    const float* W2e = (const float*)d_in[14];
    const float* g1n = (const float*)d_in[15];
    const float* b1n = (const float*)d_in[16];
    const float* g1e = (const float*)d_in[17];
    const float* b1e = (const float*)d_in[18];
    const float* g2n = (const float*)d_in[19];
    const float* b2n = (const float*)d_in[20];
    const float* g2e = (const float*)d_in[21];
    const float* b2e = (const float*)d_in[22];

    const int N = in_sizes[0] / 128;
    const int E = in_sizes[1] / 128;
    float* out = (float*)d_out;

    __half *Q, *Kb, *Vb, *PE;
    float *wV, *z;
    char* wim;
    cudaGetSymbolAddress((void**)&Q, g_Q);
    cudaGetSymbolAddress((void**)&Kb, g_Kb);
    cudaGetSymbolAddress((void**)&Vb, g_Vb);
    cudaGetSymbolAddress((void**)&PE, g_PE);
    cudaGetSymbolAddress((void**)&wV, g_wV);
    cudaGetSymbolAddress((void**)&z, g_z);
    cudaGetSymbolAddress((void**)&wim, g_wimg);

    auto IM = [&](int i) { return wim + (size_t)i * 81920; };

    const int SMG = 2 * TILEB;           // 69632
    const int SMO = 4 * TILEB + 65536;   // 204800
    cudaFuncSetAttribute((const void*)mma_gemm_ln, cudaFuncAttributeMaxDynamicSharedMemorySize, SMG);
    cudaFuncSetAttribute((const void*)out_ffn<2>, cudaFuncAttributeMaxDynamicSharedMemorySize, SMO);
    cudaFuncSetAttribute((const void*)out_ffn<3>, cudaFuncAttributeMaxDynamicSharedMemorySize, SMO);

    const int TtN = (N + 127) / 128;
    const int TtE = (E + 127) / 128;

    // 0) all weight images in one launch
    prep_all<<<dim3(128, 10), 256>>>(Wq, Wk, Wv, We, Wo_n, Wo_e, W1n, W1e, W2n, W2e, wim);

    // 1) fused LN1 + QKV projections (fp16 out; grid.y = slot 0/1/2)
    mma_gemm_ln<<<dim3(TtN, 3), 256, SMG>>>(node, g1n, b1n, IM(0), Q, Kb, Vb, N);
    // 2) fused LN1e + PE projection (fp16 out)
    mma_gemm_ln<<<dim3(TtE, 1), 256, SMG>>>(edge, g1e, b1e, IM(3), PE, PE, PE, E);

    // 3) attention aggregation
    zero2_kernel<<<2048, 256>>>(wV, (size_t)N * 128, z, (size_t)N * 8);
    edge_kernel<<<(E + 7) / 8, 256>>>(Q, Kb, Vb, PE, eidx, wV, z, E);

    // 4) fused Wo + bias + residual + LN2 + FFN + residual
    out_ffn<2><<<TtN, 256, SMO>>>(wV, z, IM(4), bo_n, node, IM(6), IM(8),
                                  g2n, b2n, out, N);
    out_ffn<3><<<TtE, 256, SMO>>>(PE, nullptr, IM(5), bo_e, edge, IM(7), IM(9),
                                  g2e, b2e, out + (size_t)N * 128, E);
}